// round 3
// baseline (speedup 1.0000x reference)
#include <cuda_runtime.h>
#include <math.h>

#define BATCH 4
#define SEQ   2048
#define DIM   512
#define NHEAD 8
#define DHEAD 64
#define MROWS (BATCH*SEQ)      // 8192
#define HB    (NHEAD*BATCH)    // 32

#define NEG_INF_F (-4294967295.0f)   // -(2^32 - 1)
#define LN_EPS 1e-8f

// Scratch (no allocation allowed in kernel_launch)
static __device__ float g_Q[MROWS*DIM];
static __device__ float g_K[MROWS*DIM];
static __device__ float g_V[MROWS*DIM];
static __device__ float g_O[MROWS*DIM];
static __device__ float g_kmask[MROWS];
static __device__ float g_qmask[MROWS];

// ---------------------------------------------------------------------------
// packed f32x2 helpers (sm_100+ fma.rn.f32x2 — 2 FMAs per instruction)
// ---------------------------------------------------------------------------
typedef unsigned long long u64;

__device__ __forceinline__ u64 pack2(float x, float y) {
    u64 r;
    asm("mov.b64 %0, {%1, %2};" : "=l"(r)
        : "r"(__float_as_uint(x)), "r"(__float_as_uint(y)));
    return r;
}
__device__ __forceinline__ void unpack2(u64 v, float& lo, float& hi) {
    unsigned a, b;
    asm("mov.b64 {%0, %1}, %2;" : "=r"(a), "=r"(b) : "l"(v));
    lo = __uint_as_float(a);
    hi = __uint_as_float(b);
}
__device__ __forceinline__ void ffma2(u64& d, u64 a, u64 b) {
    asm("fma.rn.f32x2 %0, %1, %2, %3;" : "=l"(d) : "l"(a), "l"(b), "l"(d));
}
__device__ __forceinline__ u64 fmul2(u64 a, u64 b) {
    u64 d;
    asm("mul.rn.f32x2 %0, %1, %2;" : "=l"(d) : "l"(a), "l"(b));
    return d;
}

// ---------------------------------------------------------------------------
// Masks: sign(abs(rowsum)) for keys and queries. Warp per row.
// ---------------------------------------------------------------------------
__global__ void __launch_bounds__(256) mask_kernel(const float* __restrict__ keys,
                                                   const float* __restrict__ queries)
{
    int warp = threadIdx.x >> 5;
    int lane = threadIdx.x & 31;
    int row  = blockIdx.x * 8 + warp;
    if (row >= MROWS) return;
    float sk = 0.f, sq = 0.f;
    const float* kr = keys    + (size_t)row * DIM;
    const float* qr = queries + (size_t)row * DIM;
    for (int c = lane; c < DIM; c += 32) { sk += kr[c]; sq += qr[c]; }
    #pragma unroll
    for (int o = 16; o > 0; o >>= 1) {
        sk += __shfl_xor_sync(0xffffffffu, sk, o);
        sq += __shfl_xor_sync(0xffffffffu, sq, o);
    }
    if (lane == 0) {
        g_kmask[row] = (sk != 0.0f) ? 1.0f : 0.0f;
        g_qmask[row] = (sq != 0.0f) ? 1.0f : 0.0f;
    }
}

// ---------------------------------------------------------------------------
// Projection GEMM: C[M,512] = relu(A[M,512] @ W[512,512] + bias)
// 128x128x8 tile, 256 thr, 8x8 microtile -> packed as 8x4 f32x2 pairs.
// A smem tile stored DUPLICATED so broadcast pairs are contiguous LDS.64.
// ---------------------------------------------------------------------------
__global__ void __launch_bounds__(256) proj_gemm(const float* __restrict__ A,
                                                 const float* __restrict__ W,
                                                 const float* __restrict__ bias,
                                                 float* __restrict__ C)
{
    __shared__ float Asd[8][256];   // duplicated: orig col c -> (2c, 2c+1)
    __shared__ float Bs[8][128];

    const int tid = threadIdx.x;
    const int tx  = tid & 15;
    const int ty  = tid >> 4;
    const int bm  = blockIdx.y * 128;
    const int bn  = blockIdx.x * 128;

    const int a_row = tid >> 1;          // 0..127
    const int a_col = (tid & 1) * 4;     // 0 or 4
    const int b_row = tid >> 5;          // 0..7
    const int b_col = (tid & 31) * 4;    // 0..124

    u64 accP[8][4];
    #pragma unroll
    for (int i = 0; i < 8; i++)
        #pragma unroll
        for (int j = 0; j < 4; j++) accP[i][j] = 0ull;

    // prefetch first k-tile
    float4 av = *(const float4*)&A[(size_t)(bm + a_row) * DIM + a_col];
    float4 bv = *(const float4*)&W[(size_t)b_row * DIM + bn + b_col];

    for (int k0 = 0; k0 < DIM; k0 += 8) {
        // store current tile (A duplicated)
        *(u64*)&Asd[a_col + 0][2 * a_row] = pack2(av.x, av.x);
        *(u64*)&Asd[a_col + 1][2 * a_row] = pack2(av.y, av.y);
        *(u64*)&Asd[a_col + 2][2 * a_row] = pack2(av.z, av.z);
        *(u64*)&Asd[a_col + 3][2 * a_row] = pack2(av.w, av.w);
        *(float4*)&Bs[b_row][b_col] = bv;
        __syncthreads();

        // prefetch next k-tile (redundant reload of last tile is harmless)
        int kn = (k0 + 8 < DIM) ? (k0 + 8) : k0;
        av = *(const float4*)&A[(size_t)(bm + a_row) * DIM + kn + a_col];
        bv = *(const float4*)&W[(size_t)(kn + b_row) * DIM + bn + b_col];

        #pragma unroll
        for (int kk = 0; kk < 8; kk++) {
            ulonglong2 a01 = *(const ulonglong2*)&Asd[kk][8 * ty];
            ulonglong2 a23 = *(const ulonglong2*)&Asd[kk][8 * ty + 4];
            ulonglong2 a45 = *(const ulonglong2*)&Asd[kk][128 + 8 * ty];
            ulonglong2 a67 = *(const ulonglong2*)&Asd[kk][128 + 8 * ty + 4];
            ulonglong2 b03 = *(const ulonglong2*)&Bs[kk][tx * 4];
            ulonglong2 b47 = *(const ulonglong2*)&Bs[kk][64 + tx * 4];
            u64 aP[8] = {a01.x, a01.y, a23.x, a23.y, a45.x, a45.y, a67.x, a67.y};
            u64 bP[4] = {b03.x, b03.y, b47.x, b47.y};
            #pragma unroll
            for (int i = 0; i < 8; i++)
                #pragma unroll
                for (int jp = 0; jp < 4; jp++) ffma2(accP[i][jp], aP[i], bP[jp]);
        }
        __syncthreads();
    }

    // epilogue: bias + relu
    float bsv[8];
    {
        float4 c0 = *(const float4*)&bias[bn + tx * 4];
        float4 c1 = *(const float4*)&bias[bn + 64 + tx * 4];
        bsv[0]=c0.x; bsv[1]=c0.y; bsv[2]=c0.z; bsv[3]=c0.w;
        bsv[4]=c1.x; bsv[5]=c1.y; bsv[6]=c1.z; bsv[7]=c1.w;
    }
    #pragma unroll
    for (int i = 0; i < 8; i++) {
        int row = bm + (i >> 2) * 64 + ty * 4 + (i & 3);
        #pragma unroll
        for (int j2 = 0; j2 < 2; j2++) {
            float c0, c1, c2, c3;
            unpack2(accP[i][j2 * 2 + 0], c0, c1);
            unpack2(accP[i][j2 * 2 + 1], c2, c3);
            float4 ov;
            ov.x = fmaxf(c0 + bsv[j2 * 4 + 0], 0.f);
            ov.y = fmaxf(c1 + bsv[j2 * 4 + 1], 0.f);
            ov.z = fmaxf(c2 + bsv[j2 * 4 + 2], 0.f);
            ov.w = fmaxf(c3 + bsv[j2 * 4 + 3], 0.f);
            *(float4*)&C[(size_t)row * DIM + bn + j2 * 64 + tx * 4] = ov;
        }
    }
}

// ---------------------------------------------------------------------------
// Attention: flash-style, f32x2-packed over the q dimension.
// smem: Qt[d][q] stride 68 (q-contiguous pairs for the packed operand),
//       Kd[d][2k] stride 132 (K duplicated -> broadcast pairs), union w/ Pt[k][q]
//       Vd[k][2d] stride 132 (V duplicated)
// ---------------------------------------------------------------------------
#define QT_STR 68
#define KD_STR 132
#define ATT_QT_F   (64 * QT_STR)            // 4352 floats
#define ATT_XS_F   (64 * KD_STR)            // 8448 floats (union: Kd / Pt)
#define ATT_VS_F   (64 * KD_STR)            // 8448 floats
#define ATT_SMEM_BYTES ((ATT_QT_F + ATT_XS_F + ATT_VS_F) * 4)   // 84992 B

__global__ void __launch_bounds__(256) attn_kernel(float* __restrict__ Og)
{
    extern __shared__ float sm[];
    float* Qt = sm;                         // Qt[d*68 + q]
    float* Xs = sm + ATT_QT_F;              // Kd[d*132 + 2k]  then  Pt[k*68 + q]
    float* Vd = sm + ATT_QT_F + ATT_XS_F;   // Vd[k*132 + 2d]

    const int tid  = threadIdx.x;
    const int tx   = tid & 15;
    const int ty   = tid >> 4;
    const int hb   = blockIdx.y;
    const int head = hb >> 2;            // B = 4
    const int b    = hb & 3;
    const int qt0  = blockIdx.x * 64;

    const size_t base = (size_t)b * SEQ * DIM + head * DHEAD;

    // load Q tile transposed (d-major, q contiguous)
    for (int idx = tid; idx < 64 * 64; idx += 256) {
        int q = idx >> 6, d = idx & 63;
        Qt[d * QT_STR + q] = g_Q[base + (size_t)(qt0 + q) * DIM + d];
    }

    float m[4], l[4];
    u64 oP[2][4];                        // (o[2ip][j], o[2ip+1][j])
    #pragma unroll
    for (int i = 0; i < 4; i++) { m[i] = -INFINITY; l[i] = 0.f; }
    #pragma unroll
    for (int ip = 0; ip < 2; ip++)
        #pragma unroll
        for (int j = 0; j < 4; j++) oP[ip][j] = 0ull;

    for (int kt = 0; kt < SEQ / 64; kt++) {
        const int k0 = kt * 64;
        __syncthreads();   // prev GEMM2 done with Xs/Vd
        for (int idx = tid; idx < 64 * 64; idx += 256) {
            int key = idx >> 6, d = idx & 63;
            float kvv = g_K[base + (size_t)(k0 + key) * DIM + d];
            float vvv = g_V[base + (size_t)(k0 + key) * DIM + d];
            *(u64*)&Xs[d * KD_STR + 2 * key] = pack2(kvv, kvv);  // K^T duplicated
            *(u64*)&Vd[key * KD_STR + 2 * d] = pack2(vvv, vvv);  // V duplicated
        }
        float km4[4];
        #pragma unroll
        for (int j = 0; j < 4; j++)
            km4[j] = g_kmask[b * SEQ + k0 + tx * 4 + j];
        __syncthreads();

        // GEMM1: S = Q K^T   (packed over q)
        u64 sP[2][4];
        #pragma unroll
        for (int ip = 0; ip < 2; ip++)
            #pragma unroll
            for (int j = 0; j < 4; j++) sP[ip][j] = 0ull;

        #pragma unroll 8
        for (int d = 0; d < 64; d++) {
            ulonglong2 qv = *(const ulonglong2*)&Qt[d * QT_STR + ty * 4]; // (q0,q1),(q2,q3)
            ulonglong2 ka = *(const ulonglong2*)&Xs[d * KD_STR + 8 * tx];     // (k0,k0),(k1,k1)
            ulonglong2 kb = *(const ulonglong2*)&Xs[d * KD_STR + 8 * tx + 4]; // (k2,k2),(k3,k3)
            ffma2(sP[0][0], qv.x, ka.x);
            ffma2(sP[0][1], qv.x, ka.y);
            ffma2(sP[0][2], qv.x, kb.x);
            ffma2(sP[0][3], qv.x, kb.y);
            ffma2(sP[1][0], qv.y, ka.x);
            ffma2(sP[1][1], qv.y, ka.y);
            ffma2(sP[1][2], qv.y, kb.x);
            ffma2(sP[1][3], qv.y, kb.y);
        }

        // unpack scores, scale + key mask + online softmax
        float s[4][4];
        #pragma unroll
        for (int ip = 0; ip < 2; ip++)
            #pragma unroll
            for (int j = 0; j < 4; j++)
                unpack2(sP[ip][j], s[2 * ip][j], s[2 * ip + 1][j]);

        #pragma unroll
        for (int i = 0; i < 4; i++)
            #pragma unroll
            for (int j = 0; j < 4; j++) {
                float v = s[i][j] * 0.125f;             // 1/sqrt(64)
                s[i][j] = (km4[j] == 0.0f) ? NEG_INF_F : v;
            }

        float al[4];
        #pragma unroll
        for (int i = 0; i < 4; i++) {
            float mt = fmaxf(fmaxf(s[i][0], s[i][1]), fmaxf(s[i][2], s[i][3]));
            #pragma unroll
            for (int sh = 1; sh < 16; sh <<= 1)
                mt = fmaxf(mt, __shfl_xor_sync(0xffffffffu, mt, sh));
            float mn = fmaxf(m[i], mt);
            al[i] = __expf(m[i] - mn);
            float rs = 0.f;
            #pragma unroll
            for (int j = 0; j < 4; j++) {
                float p = __expf(s[i][j] - mn);
                s[i][j] = p;
                rs += p;
            }
            #pragma unroll
            for (int sh = 1; sh < 16; sh <<= 1)
                rs += __shfl_xor_sync(0xffffffffu, rs, sh);
            l[i] = l[i] * al[i] + rs;
            m[i] = mn;
        }
        #pragma unroll
        for (int ip = 0; ip < 2; ip++) {
            u64 alp = pack2(al[2 * ip], al[2 * ip + 1]);
            #pragma unroll
            for (int j = 0; j < 4; j++) oP[ip][j] = fmul2(oP[ip][j], alp);
        }

        __syncthreads();   // done reading Xs as K
        // write P: Pt[key][q], q contiguous
        #pragma unroll
        for (int j = 0; j < 4; j++) {
            float4 pv = make_float4(s[0][j], s[1][j], s[2][j], s[3][j]);
            *(float4*)&Xs[(tx * 4 + j) * QT_STR + ty * 4] = pv;
        }
        __syncthreads();

        // GEMM2: O += P V   (packed over q)
        #pragma unroll 8
        for (int k = 0; k < 64; k++) {
            ulonglong2 pv = *(const ulonglong2*)&Xs[k * QT_STR + ty * 4];  // (p0,p1),(p2,p3)
            ulonglong2 va = *(const ulonglong2*)&Vd[k * KD_STR + 8 * tx];      // (v0,v0),(v1,v1)
            ulonglong2 vb = *(const ulonglong2*)&Vd[k * KD_STR + 8 * tx + 4];  // (v2,v2),(v3,v3)
            ffma2(oP[0][0], pv.x, va.x);
            ffma2(oP[0][1], pv.x, va.y);
            ffma2(oP[0][2], pv.x, vb.x);
            ffma2(oP[0][3], pv.x, vb.y);
            ffma2(oP[1][0], pv.y, va.x);
            ffma2(oP[1][1], pv.y, va.y);
            ffma2(oP[1][2], pv.y, vb.x);
            ffma2(oP[1][3], pv.y, vb.y);
        }
    }

    // epilogue: normalize by l, apply query mask, write merged-head layout
    float o[4][4];
    #pragma unroll
    for (int ip = 0; ip < 2; ip++)
        #pragma unroll
        for (int j = 0; j < 4; j++)
            unpack2(oP[ip][j], o[2 * ip][j], o[2 * ip + 1][j]);

    #pragma unroll
    for (int i = 0; i < 4; i++) {
        int q = qt0 + ty * 4 + i;
        float qmv = g_qmask[b * SEQ + q];
        float inv = qmv / l[i];
        float4 ov = make_float4(o[i][0] * inv, o[i][1] * inv, o[i][2] * inv, o[i][3] * inv);
        *(float4*)&Og[base + (size_t)q * DIM + tx * 4] = ov;
    }
}

// ---------------------------------------------------------------------------
// Residual + LayerNorm (ddof=1, eps added to std). Block per row, 128 threads.
// ---------------------------------------------------------------------------
__device__ __forceinline__ float block_sum_128(float v, float* red)
{
    #pragma unroll
    for (int o = 16; o > 0; o >>= 1) v += __shfl_xor_sync(0xffffffffu, v, o);
    int lane = threadIdx.x & 31, w = threadIdx.x >> 5;
    if (lane == 0) red[w] = v;
    __syncthreads();
    float t = red[0] + red[1] + red[2] + red[3];
    __syncthreads();
    return t;
}

__global__ void __launch_bounds__(128) ln_kernel(const float* __restrict__ queries,
                                                 const float* __restrict__ gamma,
                                                 const float* __restrict__ beta,
                                                 float* __restrict__ out)
{
    __shared__ float red[4];
    const int row = blockIdx.x;
    const int tid = threadIdx.x;
    const size_t rb = (size_t)row * DIM;

    float x[4];
    #pragma unroll
    for (int u = 0; u < 4; u++) {
        int c = tid + u * 128;
        x[u] = g_O[rb + c] + queries[rb + c];
    }
    float s = x[0] + x[1] + x[2] + x[3];
    float total = block_sum_128(s, red);
    float mean = total * (1.0f / DIM);

    float ss = 0.f;
    #pragma unroll
    for (int u = 0; u < 4; u++) { float d = x[u] - mean; ss += d * d; }
    float sstot = block_sum_128(ss, red);
    float var = sstot * (1.0f / (DIM - 1));
    float rden = 1.0f / (sqrtf(var) + LN_EPS);

    #pragma unroll
    for (int u = 0; u < 4; u++) {
        int c = tid + u * 128;
        out[rb + c] = gamma[c] * (x[u] - mean) * rden + beta[c];
    }
}

// ---------------------------------------------------------------------------
extern "C" void kernel_launch(void* const* d_in, const int* in_sizes, int n_in,
                              void* d_out, int out_size)
{
    const float* queries = (const float*)d_in[0];
    const float* keys    = (const float*)d_in[1];
    const float* values  = (const float*)d_in[2];
    const float* Wq      = (const float*)d_in[3];
    const float* bq      = (const float*)d_in[4];
    const float* Wk      = (const float*)d_in[5];
    const float* bk      = (const float*)d_in[6];
    const float* Wv      = (const float*)d_in[7];
    const float* bv      = (const float*)d_in[8];
    const float* gamma   = (const float*)d_in[9];
    const float* beta    = (const float*)d_in[10];
    float* out = (float*)d_out;

    float *pQ, *pK, *pV, *pO;
    cudaGetSymbolAddress((void**)&pQ, g_Q);
    cudaGetSymbolAddress((void**)&pK, g_K);
    cudaGetSymbolAddress((void**)&pV, g_V);
    cudaGetSymbolAddress((void**)&pO, g_O);

    cudaFuncSetAttribute(attn_kernel, cudaFuncAttributeMaxDynamicSharedMemorySize,
                         ATT_SMEM_BYTES);

    // 1. masks
    mask_kernel<<<MROWS / 8, 256>>>(keys, queries);

    // 2. projections
    dim3 pgrid(DIM / 128, MROWS / 128);
    proj_gemm<<<pgrid, 256>>>(queries, Wq, bq, pQ);
    proj_gemm<<<pgrid, 256>>>(keys,    Wk, bk, pK);
    proj_gemm<<<pgrid, 256>>>(values,  Wv, bv, pV);

    // 3. attention
    dim3 agrid(SEQ / 64, HB);
    attn_kernel<<<agrid, 256, ATT_SMEM_BYTES>>>(pO);

    // 4. residual + layernorm
    ln_kernel<<<MROWS, 128>>>(queries, gamma, beta, out);
}

// round 7
// speedup vs baseline: 2.6083x; 2.6083x over previous
#include <cuda_runtime.h>
#include <cuda_bf16.h>
#include <math.h>

#define BATCH 4
#define SEQ   2048
#define DIM   512
#define NHEAD 8
#define DHEAD 64
#define MROWS (BATCH*SEQ)      // 8192
#define HB    (NHEAD*BATCH)    // 32

#define NEG_INF_F (-4294967295.0f)   // -(2^32 - 1)
#define LN_EPS 1e-8f

typedef unsigned int u32;

// ---------------------------------------------------------------------------
// Scratch (no allocation allowed in kernel_launch)
// ---------------------------------------------------------------------------
static __device__ __nv_bfloat16 g_Qhi[MROWS*DIM];
static __device__ __nv_bfloat16 g_Qlo[MROWS*DIM];
static __device__ __nv_bfloat16 g_Khi[MROWS*DIM];
static __device__ __nv_bfloat16 g_Klo[MROWS*DIM];
static __device__ __nv_bfloat16 g_Vhi[MROWS*DIM];
static __device__ __nv_bfloat16 g_Vlo[MROWS*DIM];
static __device__ float g_O[MROWS*DIM];
static __device__ float g_kmask[MROWS];
static __device__ float g_qmask[MROWS];

// ---------------------------------------------------------------------------
// mma.sync / ldmatrix helpers (arch-generic PTX, runs on HMMA tensor pipe)
// ---------------------------------------------------------------------------
__device__ __forceinline__ u32 smem_u32(const void* p) {
    u32 a;
    asm("{ .reg .u64 t; cvta.to.shared.u64 t, %1; cvt.u32.u64 %0, t; }" : "=r"(a) : "l"(p));
    return a;
}
__device__ __forceinline__ void ldm4(u32 addr, u32& r0, u32& r1, u32& r2, u32& r3) {
    asm volatile("ldmatrix.sync.aligned.m8n8.x4.shared.b16 {%0,%1,%2,%3}, [%4];"
                 : "=r"(r0), "=r"(r1), "=r"(r2), "=r"(r3) : "r"(addr));
}
__device__ __forceinline__ void ldm4t(u32 addr, u32& r0, u32& r1, u32& r2, u32& r3) {
    asm volatile("ldmatrix.sync.aligned.m8n8.x4.trans.shared.b16 {%0,%1,%2,%3}, [%4];"
                 : "=r"(r0), "=r"(r1), "=r"(r2), "=r"(r3) : "r"(addr));
}
__device__ __forceinline__ void mma16816(float d[4], u32 a0, u32 a1, u32 a2, u32 a3,
                                         u32 b0, u32 b1) {
    asm volatile("mma.sync.aligned.m16n8k16.row.col.f32.bf16.bf16.f32 "
                 "{%0,%1,%2,%3}, {%4,%5,%6,%7}, {%8,%9}, {%0,%1,%2,%3};"
                 : "+f"(d[0]), "+f"(d[1]), "+f"(d[2]), "+f"(d[3])
                 : "r"(a0), "r"(a1), "r"(a2), "r"(a3), "r"(b0), "r"(b1));
}
__device__ __forceinline__ u32 pack_pair(float lo, float hi) {
    __nv_bfloat162 t = __halves2bfloat162(__float2bfloat16(lo), __float2bfloat16(hi));
    return *(u32*)&t;
}

// ---------------------------------------------------------------------------
// Masks: sign(abs(rowsum)) for keys and queries. Warp per row.
// ---------------------------------------------------------------------------
__global__ void __launch_bounds__(256) mask_kernel(const float* __restrict__ keys,
                                                   const float* __restrict__ queries)
{
    int warp = threadIdx.x >> 5;
    int lane = threadIdx.x & 31;
    int row  = blockIdx.x * 8 + warp;
    if (row >= MROWS) return;
    float sk = 0.f, sq = 0.f;
    const float* kr = keys    + (size_t)row * DIM;
    const float* qr = queries + (size_t)row * DIM;
    for (int c = lane; c < DIM; c += 32) { sk += kr[c]; sq += qr[c]; }
    #pragma unroll
    for (int o = 16; o > 0; o >>= 1) {
        sk += __shfl_xor_sync(0xffffffffu, sk, o);
        sq += __shfl_xor_sync(0xffffffffu, sq, o);
    }
    if (lane == 0) {
        g_kmask[row] = (sk != 0.0f) ? 1.0f : 0.0f;
        g_qmask[row] = (sq != 0.0f) ? 1.0f : 0.0f;
    }
}

// ---------------------------------------------------------------------------
// Projection GEMM (R1-proven SIMT): C = relu(A @ W + b), epilogue -> bf16 hi/lo
// ---------------------------------------------------------------------------
__global__ void __launch_bounds__(256) proj_gemm(const float* __restrict__ A,
                                                 const float* __restrict__ W,
                                                 const float* __restrict__ bias,
                                                 __nv_bfloat16* __restrict__ Chi,
                                                 __nv_bfloat16* __restrict__ Clo)
{
    __shared__ float As[8][128];
    __shared__ float Bs[8][128];

    const int tid = threadIdx.x;
    const int tx  = tid & 15;
    const int ty  = tid >> 4;
    const int bm  = blockIdx.y * 128;
    const int bn  = blockIdx.x * 128;

    const int a_row = tid >> 1;
    const int a_col = (tid & 1) * 4;
    const int b_row = tid >> 5;
    const int b_col = (tid & 31) * 4;

    float acc[8][8];
    #pragma unroll
    for (int i = 0; i < 8; i++)
        #pragma unroll
        for (int j = 0; j < 8; j++) acc[i][j] = 0.f;

    for (int k0 = 0; k0 < DIM; k0 += 8) {
        float4 av = *(const float4*)&A[(size_t)(bm + a_row) * DIM + k0 + a_col];
        As[a_col + 0][a_row] = av.x;
        As[a_col + 1][a_row] = av.y;
        As[a_col + 2][a_row] = av.z;
        As[a_col + 3][a_row] = av.w;
        float4 bv = *(const float4*)&W[(size_t)(k0 + b_row) * DIM + bn + b_col];
        *(float4*)&Bs[b_row][b_col] = bv;
        __syncthreads();

        #pragma unroll
        for (int kk = 0; kk < 8; kk++) {
            float4 a0 = *(const float4*)&As[kk][ty * 4];
            float4 a1 = *(const float4*)&As[kk][64 + ty * 4];
            float4 b0 = *(const float4*)&Bs[kk][tx * 4];
            float4 b1 = *(const float4*)&Bs[kk][64 + tx * 4];
            float ar[8] = {a0.x, a0.y, a0.z, a0.w, a1.x, a1.y, a1.z, a1.w};
            float br[8] = {b0.x, b0.y, b0.z, b0.w, b1.x, b1.y, b1.z, b1.w};
            #pragma unroll
            for (int i = 0; i < 8; i++)
                #pragma unroll
                for (int j = 0; j < 8; j++) acc[i][j] += ar[i] * br[j];
        }
        __syncthreads();
    }

    float bsv[8];
    {
        float4 c0 = *(const float4*)&bias[bn + tx * 4];
        float4 c1 = *(const float4*)&bias[bn + 64 + tx * 4];
        bsv[0]=c0.x; bsv[1]=c0.y; bsv[2]=c0.z; bsv[3]=c0.w;
        bsv[4]=c1.x; bsv[5]=c1.y; bsv[6]=c1.z; bsv[7]=c1.w;
    }
    #pragma unroll
    for (int i = 0; i < 8; i++) {
        int row = bm + (i >> 2) * 64 + ty * 4 + (i & 3);
        #pragma unroll
        for (int j2 = 0; j2 < 2; j2++) {
            u32 hp[2], lp[2];
            #pragma unroll
            for (int jp = 0; jp < 2; jp++) {
                float v0 = fmaxf(acc[i][j2*4 + jp*2 + 0] + bsv[j2*4 + jp*2 + 0], 0.f);
                float v1 = fmaxf(acc[i][j2*4 + jp*2 + 1] + bsv[j2*4 + jp*2 + 1], 0.f);
                __nv_bfloat16 h0 = __float2bfloat16(v0);
                __nv_bfloat16 h1 = __float2bfloat16(v1);
                float r0 = v0 - __bfloat162float(h0);
                float r1 = v1 - __bfloat162float(h1);
                __nv_bfloat162 hh = __halves2bfloat162(h0, h1);
                __nv_bfloat162 ll = __halves2bfloat162(__float2bfloat16(r0), __float2bfloat16(r1));
                hp[jp] = *(u32*)&hh;
                lp[jp] = *(u32*)&ll;
            }
            size_t off = (size_t)row * DIM + bn + j2 * 64 + tx * 4;
            *(uint2*)&Chi[off] = make_uint2(hp[0], hp[1]);
            *(uint2*)&Clo[off] = make_uint2(lp[0], lp[1]);
        }
    }
}

// ---------------------------------------------------------------------------
// mma.sync flash attention.
// CTA: 256 thr (8 warps), 128 q-rows x one hb; key tiles of 64.
// Warp w owns q rows w*16..w*16+15; per-thread rows g=lane>>2 and g+8.
// smem (bf16, row stride 72 elems = 144 B):
//   Qhi[128][72], Qlo[128][72], Khi[64][72], Klo, Vhi, Vlo, kmask[64]
// ---------------------------------------------------------------------------
#define RS    72                       // row stride (elements)
#define SMB_QHI 0
#define SMB_QLO (SMB_QHI + 128*RS*2)   // 18432
#define SMB_KHI (SMB_QLO + 128*RS*2)   // 36864
#define SMB_KLO (SMB_KHI + 64*RS*2)    // 46080
#define SMB_VHI (SMB_KLO + 64*RS*2)    // 55296
#define SMB_VLO (SMB_VHI + 64*RS*2)    // 64512
#define SMB_KM  (SMB_VLO + 64*RS*2)    // 73728
#define ATT_SMEM (SMB_KM + 64*4)       // 73984

__global__ void __launch_bounds__(256, 2) attn_kernel(float* __restrict__ Og)
{
    extern __shared__ char smc[];
    const u32 sb = smem_u32(smc);

    const int tid  = threadIdx.x;
    const int warp = tid >> 5;
    const int lane = tid & 31;
    const int g    = lane >> 2;          // row group 0..7
    const int t4   = lane & 3;           // col pair index
    const int hb   = blockIdx.y;
    const int head = hb >> 2;
    const int b    = hb & 3;
    const int qt0  = blockIdx.x * 128;

    float* ksm = (float*)(smc + SMB_KM);

    // ---- load Q tile (128 x 64) hi/lo ----
    {
        const uint4* qh4 = (const uint4*)g_Qhi;
        const uint4* ql4 = (const uint4*)g_Qlo;
        #pragma unroll
        for (int it = 0; it < 4; it++) {
            int c = it * 256 + tid;      // 0..1023
            int q = c >> 3, dc = c & 7;
            size_t gi = ((size_t)(b * SEQ + qt0 + q) * DIM + head * DHEAD) / 8 + dc;
            *(uint4*)(smc + SMB_QHI + q * (RS*2) + dc * 16) = qh4[gi];
            *(uint4*)(smc + SMB_QLO + q * (RS*2) + dc * 16) = ql4[gi];
        }
    }

    // ldmatrix address lanes (byte offsets into row-major [r][RS] bf16)
    // A-frag (Q): row = warp*16 + (lane&15), col base +(lane>>4)*8
    const u32 aoff = (u32)((warp * 16 + (lane & 15)) * (RS*2) + ((lane >> 4) << 3) * 2);
    // B-frag (K): key = (lane&7) + ((lane>>4)<<3), col +((lane>>3)&1)*8
    const u32 boff = (u32)((((lane & 7) + ((lane >> 4) << 3)) * (RS*2)) + ((((lane >> 3) & 1) << 3) * 2));
    // B-frag trans (V): key = (lane&7) + (lane&8), col +(lane>>4)*8
    const u32 voff = (u32)((((lane & 7) + (lane & 8)) * (RS*2)) + (((lane >> 4) << 3) * 2));

    float m0 = NEG_INF_F, m1 = NEG_INF_F, l0 = 0.f, l1 = 0.f;
    float oacc[8][4];
    #pragma unroll
    for (int j = 0; j < 8; j++)
        #pragma unroll
        for (int c = 0; c < 4; c++) oacc[j][c] = 0.f;

    for (int kt = 0; kt < SEQ / 64; kt++) {
        const int k0 = kt * 64;
        __syncthreads();   // prev tile's V reads done

        // ---- load K/V tiles (64 x 64) hi/lo ----
        {
            const uint4* kh4 = (const uint4*)g_Khi;
            const uint4* kl4 = (const uint4*)g_Klo;
            const uint4* vh4 = (const uint4*)g_Vhi;
            const uint4* vl4 = (const uint4*)g_Vlo;
            #pragma unroll
            for (int it = 0; it < 2; it++) {
                int c = it * 256 + tid;  // 0..511
                int r = c >> 3, dc = c & 7;
                size_t gi = ((size_t)(b * SEQ + k0 + r) * DIM + head * DHEAD) / 8 + dc;
                u32 so = (u32)(r * (RS*2) + dc * 16);
                *(uint4*)(smc + SMB_KHI + so) = kh4[gi];
                *(uint4*)(smc + SMB_KLO + so) = kl4[gi];
                *(uint4*)(smc + SMB_VHI + so) = vh4[gi];
                *(uint4*)(smc + SMB_VLO + so) = vl4[gi];
            }
            if (tid < 64) ksm[tid] = g_kmask[b * SEQ + k0 + tid];
        }
        __syncthreads();

        // ---- GEMM1: S[16x64] = Q K^T (hi*hi + hi*lo + lo*hi) ----
        float sacc[8][4];
        #pragma unroll
        for (int j = 0; j < 8; j++)
            #pragma unroll
            for (int c = 0; c < 4; c++) sacc[j][c] = 0.f;

        #pragma unroll
        for (int kk = 0; kk < 4; kk++) {
            u32 qh[4], ql[4];
            ldm4(sb + SMB_QHI + aoff + kk * 32, qh[0], qh[1], qh[2], qh[3]);
            ldm4(sb + SMB_QLO + aoff + kk * 32, ql[0], ql[1], ql[2], ql[3]);
            #pragma unroll
            for (int nt2 = 0; nt2 < 4; nt2++) {
                u32 kh[4], kl[4];
                u32 ko = boff + nt2 * 16 * (RS*2) + kk * 32;
                ldm4(sb + SMB_KHI + ko, kh[0], kh[1], kh[2], kh[3]);
                ldm4(sb + SMB_KLO + ko, kl[0], kl[1], kl[2], kl[3]);
                mma16816(sacc[2*nt2],   qh[0], qh[1], qh[2], qh[3], kh[0], kh[1]);
                mma16816(sacc[2*nt2],   qh[0], qh[1], qh[2], qh[3], kl[0], kl[1]);
                mma16816(sacc[2*nt2],   ql[0], ql[1], ql[2], ql[3], kh[0], kh[1]);
                mma16816(sacc[2*nt2+1], qh[0], qh[1], qh[2], qh[3], kh[2], kh[3]);
                mma16816(sacc[2*nt2+1], qh[0], qh[1], qh[2], qh[3], kl[2], kl[3]);
                mma16816(sacc[2*nt2+1], ql[0], ql[1], ql[2], ql[3], kh[2], kh[3]);
            }
        }

        // ---- scale + key mask ----
        #pragma unroll
        for (int j = 0; j < 8; j++) {
            float km0 = ksm[8*j + 2*t4];
            float km1 = ksm[8*j + 2*t4 + 1];
            sacc[j][0] = (km0 == 0.f) ? NEG_INF_F : sacc[j][0] * 0.125f;
            sacc[j][1] = (km1 == 0.f) ? NEG_INF_F : sacc[j][1] * 0.125f;
            sacc[j][2] = (km0 == 0.f) ? NEG_INF_F : sacc[j][2] * 0.125f;
            sacc[j][3] = (km1 == 0.f) ? NEG_INF_F : sacc[j][3] * 0.125f;
        }

        // ---- online softmax (rows g and g+8, warp-local) ----
        float mx0 = NEG_INF_F, mx1 = NEG_INF_F;
        #pragma unroll
        for (int j = 0; j < 8; j++) {
            mx0 = fmaxf(mx0, fmaxf(sacc[j][0], sacc[j][1]));
            mx1 = fmaxf(mx1, fmaxf(sacc[j][2], sacc[j][3]));
        }
        mx0 = fmaxf(mx0, __shfl_xor_sync(0xffffffffu, mx0, 1));
        mx0 = fmaxf(mx0, __shfl_xor_sync(0xffffffffu, mx0, 2));
        mx1 = fmaxf(mx1, __shfl_xor_sync(0xffffffffu, mx1, 1));
        mx1 = fmaxf(mx1, __shfl_xor_sync(0xffffffffu, mx1, 2));

        float mn0 = fmaxf(m0, mx0), mn1 = fmaxf(m1, mx1);
        float a0 = __expf(m0 - mn0), a1 = __expf(m1 - mn1);
        m0 = mn0; m1 = mn1;

        float s0 = 0.f, s1 = 0.f;
        #pragma unroll
        for (int j = 0; j < 8; j++) {
            float p0 = __expf(sacc[j][0] - mn0);
            float p1 = __expf(sacc[j][1] - mn0);
            float p2 = __expf(sacc[j][2] - mn1);
            float p3 = __expf(sacc[j][3] - mn1);
            sacc[j][0] = p0; sacc[j][1] = p1; sacc[j][2] = p2; sacc[j][3] = p3;
            s0 += p0 + p1; s1 += p2 + p3;
        }
        s0 += __shfl_xor_sync(0xffffffffu, s0, 1);
        s0 += __shfl_xor_sync(0xffffffffu, s0, 2);
        s1 += __shfl_xor_sync(0xffffffffu, s1, 1);
        s1 += __shfl_xor_sync(0xffffffffu, s1, 2);
        l0 = l0 * a0 + s0;
        l1 = l1 * a1 + s1;

        #pragma unroll
        for (int j = 0; j < 8; j++) {
            oacc[j][0] *= a0; oacc[j][1] *= a0;
            oacc[j][2] *= a1; oacc[j][3] *= a1;
        }

        // ---- GEMM2: O += P V (hi*hi + hi*lo + lo*hi); P frags built per k-step ----
        #pragma unroll
        for (int kk = 0; kk < 4; kk++) {
            // A-frag from S-accumulator layout (register-to-register)
            u32 ph[4], pl[4];
            #pragma unroll
            for (int h = 0; h < 2; h++) {
                int j = 2 * kk + h;
                float p0 = sacc[j][0], p1 = sacc[j][1], p2 = sacc[j][2], p3 = sacc[j][3];
                u32 h01 = pack_pair(p0, p1);
                u32 h23 = pack_pair(p2, p3);
                __nv_bfloat162 b01 = *(__nv_bfloat162*)&h01;
                __nv_bfloat162 b23 = *(__nv_bfloat162*)&h23;
                ph[2*h + 0] = h01;
                ph[2*h + 1] = h23;
                pl[2*h + 0] = pack_pair(p0 - __bfloat162float(b01.x),
                                        p1 - __bfloat162float(b01.y));
                pl[2*h + 1] = pack_pair(p2 - __bfloat162float(b23.x),
                                        p3 - __bfloat162float(b23.y));
            }
            // A ordering: a0a1 = ntile even c0c1, a2a3 = even c2c3,
            //             a4a5 = ntile odd c0c1, a6a7 = odd c2c3
            u32 A0 = ph[0], A1 = ph[1], A2 = ph[2], A3 = ph[3];
            u32 L0 = pl[0], L1 = pl[1], L2 = pl[2], L3 = pl[3];

            #pragma unroll
            for (int dt2 = 0; dt2 < 4; dt2++) {
                u32 vh[4], vl[4];
                u32 vo = voff + kk * 16 * (RS*2) + dt2 * 32;
                ldm4t(sb + SMB_VHI + vo, vh[0], vh[1], vh[2], vh[3]);
                ldm4t(sb + SMB_VLO + vo, vl[0], vl[1], vl[2], vl[3]);
                mma16816(oacc[2*dt2],   A0, A1, A2, A3, vh[0], vh[1]);
                mma16816(oacc[2*dt2],   A0, A1, A2, A3, vl[0], vl[1]);
                mma16816(oacc[2*dt2],   L0, L1, L2, L3, vh[0], vh[1]);
                mma16816(oacc[2*dt2+1], A0, A1, A2, A3, vh[2], vh[3]);
                mma16816(oacc[2*dt2+1], A0, A1, A2, A3, vl[2], vl[3]);
                mma16816(oacc[2*dt2+1], L0, L1, L2, L3, vh[2], vh[3]);
            }
        }
    }

    // ---- epilogue: normalize, query mask, write ----
    {
        int q0 = qt0 + warp * 16 + g;
        int q1 = q0 + 8;
        float inv0 = g_qmask[b * SEQ + q0] / l0;
        float inv1 = g_qmask[b * SEQ + q1] / l1;
        size_t base0 = (size_t)(b * SEQ + q0) * DIM + head * DHEAD;
        size_t base1 = (size_t)(b * SEQ + q1) * DIM + head * DHEAD;
        #pragma unroll
        for (int j = 0; j < 8; j++) {
            int d = 8 * j + 2 * t4;
            *(float2*)&Og[base0 + d] = make_float2(oacc[j][0] * inv0, oacc[j][1] * inv0);
            *(float2*)&Og[base1 + d] = make_float2(oacc[j][2] * inv1, oacc[j][3] * inv1);
        }
    }
}

// ---------------------------------------------------------------------------
// Residual + LayerNorm (ddof=1, eps added to std). Block per row, 128 threads.
// ---------------------------------------------------------------------------
__device__ __forceinline__ float block_sum_128(float v, float* red)
{
    #pragma unroll
    for (int o = 16; o > 0; o >>= 1) v += __shfl_xor_sync(0xffffffffu, v, o);
    int lane = threadIdx.x & 31, w = threadIdx.x >> 5;
    if (lane == 0) red[w] = v;
    __syncthreads();
    float t = red[0] + red[1] + red[2] + red[3];
    __syncthreads();
    return t;
}

__global__ void __launch_bounds__(128) ln_kernel(const float* __restrict__ queries,
                                                 const float* __restrict__ gamma,
                                                 const float* __restrict__ beta,
                                                 float* __restrict__ out)
{
    __shared__ float red[4];
    const int row = blockIdx.x;
    const int tid = threadIdx.x;
    const size_t rb = (size_t)row * DIM;

    float x[4];
    #pragma unroll
    for (int u = 0; u < 4; u++) {
        int c = tid + u * 128;
        x[u] = g_O[rb + c] + queries[rb + c];
    }
    float s = x[0] + x[1] + x[2] + x[3];
    float total = block_sum_128(s, red);
    float mean = total * (1.0f / DIM);

    float ss = 0.f;
    #pragma unroll
    for (int u = 0; u < 4; u++) { float d = x[u] - mean; ss += d * d; }
    float sstot = block_sum_128(ss, red);
    float var = sstot * (1.0f / (DIM - 1));
    float rden = 1.0f / (sqrtf(var) + LN_EPS);

    #pragma unroll
    for (int u = 0; u < 4; u++) {
        int c = tid + u * 128;
        out[rb + c] = gamma[c] * (x[u] - mean) * rden + beta[c];
    }
}

// ---------------------------------------------------------------------------
extern "C" void kernel_launch(void* const* d_in, const int* in_sizes, int n_in,
                              void* d_out, int out_size)
{
    const float* queries = (const float*)d_in[0];
    const float* keys    = (const float*)d_in[1];
    const float* values  = (const float*)d_in[2];
    const float* Wq      = (const float*)d_in[3];
    const float* bq      = (const float*)d_in[4];
    const float* Wk      = (const float*)d_in[5];
    const float* bk      = (const float*)d_in[6];
    const float* Wv      = (const float*)d_in[7];
    const float* bv      = (const float*)d_in[8];
    const float* gamma   = (const float*)d_in[9];
    const float* beta    = (const float*)d_in[10];
    float* out = (float*)d_out;

    __nv_bfloat16 *pQh, *pQl, *pKh, *pKl, *pVh, *pVl;
    float* pO;
    cudaGetSymbolAddress((void**)&pQh, g_Qhi);
    cudaGetSymbolAddress((void**)&pQl, g_Qlo);
    cudaGetSymbolAddress((void**)&pKh, g_Khi);
    cudaGetSymbolAddress((void**)&pKl, g_Klo);
    cudaGetSymbolAddress((void**)&pVh, g_Vhi);
    cudaGetSymbolAddress((void**)&pVl, g_Vlo);
    cudaGetSymbolAddress((void**)&pO,  g_O);

    cudaFuncSetAttribute(attn_kernel, cudaFuncAttributeMaxDynamicSharedMemorySize, ATT_SMEM);

    // 1. masks
    mask_kernel<<<MROWS / 8, 256>>>(keys, queries);

    // 2. projections (fp32 SIMT GEMM, bf16 hi/lo epilogue)
    dim3 pgrid(DIM / 128, MROWS / 128);
    proj_gemm<<<pgrid, 256>>>(queries, Wq, bq, pQh, pQl);
    proj_gemm<<<pgrid, 256>>>(keys,    Wk, bk, pKh, pKl);
    proj_gemm<<<pgrid, 256>>>(values,  Wv, bv, pVh, pVl);

    // 3. mma.sync flash attention
    attn_kernel<<<dim3(SEQ / 128, HB), 256, ATT_SMEM>>>(pO);

    // 4. residual + layernorm
    ln_kernel<<<MROWS, 128>>>(queries, gamma, beta, out);
}

// round 8
// speedup vs baseline: 5.2592x; 2.0164x over previous
#include <cuda_runtime.h>
#include <cuda_bf16.h>
#include <math.h>

#define BATCH 4
#define SEQ   2048
#define DIM   512
#define NHEAD 8
#define DHEAD 64
#define MROWS (BATCH*SEQ)      // 8192
#define HB    (NHEAD*BATCH)    // 32

#define NEG_INF_F (-4294967295.0f)   // -(2^32 - 1)
#define LN_EPS 1e-8f

typedef unsigned int u32;

// ---------------------------------------------------------------------------
// Scratch (no allocation allowed in kernel_launch)
// ---------------------------------------------------------------------------
static __device__ __nv_bfloat16 g_Qhi[MROWS*DIM];
static __device__ __nv_bfloat16 g_Qlo[MROWS*DIM];
static __device__ __nv_bfloat16 g_Khi[MROWS*DIM];
static __device__ __nv_bfloat16 g_Klo[MROWS*DIM];
static __device__ __nv_bfloat16 g_Vhi[MROWS*DIM];
static __device__ __nv_bfloat16 g_Vlo[MROWS*DIM];
static __device__ float g_O[MROWS*DIM];
static __device__ float g_kmask[MROWS];
static __device__ float g_qmask[MROWS];

// ---------------------------------------------------------------------------
// mma.sync / ldmatrix helpers (arch-generic PTX, runs on HMMA tensor pipe)
// ---------------------------------------------------------------------------
__device__ __forceinline__ u32 smem_u32(const void* p) {
    u32 a;
    asm("{ .reg .u64 t; cvta.to.shared.u64 t, %1; cvt.u32.u64 %0, t; }" : "=r"(a) : "l"(p));
    return a;
}
__device__ __forceinline__ void ldm4(u32 addr, u32& r0, u32& r1, u32& r2, u32& r3) {
    asm volatile("ldmatrix.sync.aligned.m8n8.x4.shared.b16 {%0,%1,%2,%3}, [%4];"
                 : "=r"(r0), "=r"(r1), "=r"(r2), "=r"(r3) : "r"(addr));
}
__device__ __forceinline__ void ldm4t(u32 addr, u32& r0, u32& r1, u32& r2, u32& r3) {
    asm volatile("ldmatrix.sync.aligned.m8n8.x4.trans.shared.b16 {%0,%1,%2,%3}, [%4];"
                 : "=r"(r0), "=r"(r1), "=r"(r2), "=r"(r3) : "r"(addr));
}
__device__ __forceinline__ void mma16816(float d[4], u32 a0, u32 a1, u32 a2, u32 a3,
                                         u32 b0, u32 b1) {
    asm volatile("mma.sync.aligned.m16n8k16.row.col.f32.bf16.bf16.f32 "
                 "{%0,%1,%2,%3}, {%4,%5,%6,%7}, {%8,%9}, {%0,%1,%2,%3};"
                 : "+f"(d[0]), "+f"(d[1]), "+f"(d[2]), "+f"(d[3])
                 : "r"(a0), "r"(a1), "r"(a2), "r"(a3), "r"(b0), "r"(b1));
}
__device__ __forceinline__ u32 pack_pair(float lo, float hi) {
    __nv_bfloat162 t = __halves2bfloat162(__float2bfloat16(lo), __float2bfloat16(hi));
    return *(u32*)&t;
}
// split v -> hi pair / lo pair (packed u32 of 2 bf16)
__device__ __forceinline__ void split_pair(float v0, float v1, u32& hi, u32& lo) {
    __nv_bfloat16 h0 = __float2bfloat16(v0);
    __nv_bfloat16 h1 = __float2bfloat16(v1);
    __nv_bfloat162 hh = __halves2bfloat162(h0, h1);
    __nv_bfloat162 ll = __halves2bfloat162(__float2bfloat16(v0 - __bfloat162float(h0)),
                                           __float2bfloat16(v1 - __bfloat162float(h1)));
    hi = *(u32*)&hh;
    lo = *(u32*)&ll;
}

// ---------------------------------------------------------------------------
// Masks: sign(abs(rowsum)) for keys and queries. Warp per row.
// ---------------------------------------------------------------------------
__global__ void __launch_bounds__(256) mask_kernel(const float* __restrict__ keys,
                                                   const float* __restrict__ queries)
{
    int warp = threadIdx.x >> 5;
    int lane = threadIdx.x & 31;
    int row  = blockIdx.x * 8 + warp;
    if (row >= MROWS) return;
    float sk = 0.f, sq = 0.f;
    const float* kr = keys    + (size_t)row * DIM;
    const float* qr = queries + (size_t)row * DIM;
    for (int c = lane; c < DIM; c += 32) { sk += kr[c]; sq += qr[c]; }
    #pragma unroll
    for (int o = 16; o > 0; o >>= 1) {
        sk += __shfl_xor_sync(0xffffffffu, sk, o);
        sq += __shfl_xor_sync(0xffffffffu, sq, o);
    }
    if (lane == 0) {
        g_kmask[row] = (sk != 0.0f) ? 1.0f : 0.0f;
        g_qmask[row] = (sq != 0.0f) ? 1.0f : 0.0f;
    }
}

// ---------------------------------------------------------------------------
// Projection GEMM on the tensor pipe: C = relu(A @ W + b), bf16 hi/lo 3-product.
// CTA 128x128, 8 warps (4 row x 2 col), warp tile 32x64, k-chunks of 32.
// A [8192,512] fp32, W [512,512] fp32 (k-major rows) -> split to smem on the fly.
// ---------------------------------------------------------------------------
#define PA_RS 40    // A smem row stride (elements)
#define PW_RS 136   // W smem row stride (elements)

__global__ void __launch_bounds__(256, 2) proj_mma(const float* __restrict__ A,
                                                   const float* __restrict__ W,
                                                   const float* __restrict__ bias,
                                                   __nv_bfloat16* __restrict__ Chi,
                                                   __nv_bfloat16* __restrict__ Clo)
{
    __shared__ __nv_bfloat16 sAh[128 * PA_RS];
    __shared__ __nv_bfloat16 sAl[128 * PA_RS];
    __shared__ __nv_bfloat16 sWh[32 * PW_RS];
    __shared__ __nv_bfloat16 sWl[32 * PW_RS];

    const int tid  = threadIdx.x;
    const int warp = tid >> 5;
    const int lane = tid & 31;
    const int g    = lane >> 2;
    const int t4   = lane & 3;
    const int wr   = warp & 3;           // warp row: rows wr*32..+31
    const int wc   = warp >> 2;          // warp col: cols wc*64..+63
    const int bm   = blockIdx.y * 128;
    const int bn   = blockIdx.x * 128;

    const u32 sbAh = smem_u32(sAh);
    const u32 sbAl = smem_u32(sAl);
    const u32 sbWh = smem_u32(sWh);
    const u32 sbWl = smem_u32(sWl);

    // ldmatrix lane offsets (bytes)
    // A frag (row-major): row = wr*32 + mt*16 + (lane&15), col +(lane>>4)*8
    const u32 aoff = (u32)(((wr * 32 + (lane & 15)) * PA_RS + ((lane >> 4) << 3)) * 2);
    // W frag (trans on [k][n]): k = (lane&7)+(lane&8), n = wc*64 + nt2*16 + (lane>>4)*8
    const u32 woff = (u32)(((((lane & 7) + (lane & 8)) * PW_RS) +
                            wc * 64 + (((lane >> 4) << 3))) * 2);

    float acc[2][8][4];
    #pragma unroll
    for (int mt = 0; mt < 2; mt++)
        #pragma unroll
        for (int nt = 0; nt < 8; nt++)
            #pragma unroll
            for (int c = 0; c < 4; c++) acc[mt][nt][c] = 0.f;

    // loader indices
    const int a_row = tid >> 1;              // 0..127 (2 thr/row, 4 float4/row each)
    const int a_c4  = (tid & 1) * 4;         // float4 index base 0 or 4
    const int w_row = tid >> 3;              // 0..31 (8 thr/row, 4 float4/row each)
    const int w_c4  = (tid & 7) * 4;

    for (int k0 = 0; k0 < DIM; k0 += 32) {
        // ---- global loads to regs ----
        float4 av[4], wv[4];
        #pragma unroll
        for (int u = 0; u < 4; u++)
            av[u] = *(const float4*)&A[(size_t)(bm + a_row) * DIM + k0 + (a_c4 + u) * 4];
        #pragma unroll
        for (int u = 0; u < 4; u++)
            wv[u] = *(const float4*)&W[(size_t)(k0 + w_row) * DIM + bn + (w_c4 + u) * 4];

        __syncthreads();   // prev chunk's ldmatrix reads done

        // ---- split + store to smem ----
        #pragma unroll
        for (int u = 0; u < 4; u++) {
            u32 h0, l0, h1, l1;
            split_pair(av[u].x, av[u].y, h0, l0);
            split_pair(av[u].z, av[u].w, h1, l1);
            int e = a_row * PA_RS + (a_c4 + u) * 4;
            *(uint2*)&sAh[e] = make_uint2(h0, h1);
            *(uint2*)&sAl[e] = make_uint2(l0, l1);
            split_pair(wv[u].x, wv[u].y, h0, l0);
            split_pair(wv[u].z, wv[u].w, h1, l1);
            e = w_row * PW_RS + (w_c4 + u) * 4;
            *(uint2*)&sWh[e] = make_uint2(h0, h1);
            *(uint2*)&sWl[e] = make_uint2(l0, l1);
        }
        __syncthreads();

        // ---- mma over 2 k16 steps ----
        #pragma unroll
        for (int kk = 0; kk < 2; kk++) {
            u32 ah[2][4], al[2][4];
            #pragma unroll
            for (int mt = 0; mt < 2; mt++) {
                u32 ao = aoff + (u32)((mt * 16 * PA_RS + kk * 16) * 2);
                ldm4(sbAh + ao, ah[mt][0], ah[mt][1], ah[mt][2], ah[mt][3]);
                ldm4(sbAl + ao, al[mt][0], al[mt][1], al[mt][2], al[mt][3]);
            }
            #pragma unroll
            for (int nt2 = 0; nt2 < 4; nt2++) {
                u32 wh[4], wl[4];
                u32 wo = woff + (u32)((kk * 16 * PW_RS + nt2 * 16) * 2);
                ldm4t(sbWh + wo, wh[0], wh[1], wh[2], wh[3]);
                ldm4t(sbWl + wo, wl[0], wl[1], wl[2], wl[3]);
                #pragma unroll
                for (int mt = 0; mt < 2; mt++) {
                    mma16816(acc[mt][2*nt2],   ah[mt][0], ah[mt][1], ah[mt][2], ah[mt][3], wh[0], wh[1]);
                    mma16816(acc[mt][2*nt2],   ah[mt][0], ah[mt][1], ah[mt][2], ah[mt][3], wl[0], wl[1]);
                    mma16816(acc[mt][2*nt2],   al[mt][0], al[mt][1], al[mt][2], al[mt][3], wh[0], wh[1]);
                    mma16816(acc[mt][2*nt2+1], ah[mt][0], ah[mt][1], ah[mt][2], ah[mt][3], wh[2], wh[3]);
                    mma16816(acc[mt][2*nt2+1], ah[mt][0], ah[mt][1], ah[mt][2], ah[mt][3], wl[2], wl[3]);
                    mma16816(acc[mt][2*nt2+1], al[mt][0], al[mt][1], al[mt][2], al[mt][3], wh[2], wh[3]);
                }
            }
        }
    }

    // ---- epilogue: bias + relu, split to bf16 hi/lo ----
    #pragma unroll
    for (int mt = 0; mt < 2; mt++) {
        int r0 = bm + wr * 32 + mt * 16 + g;
        int r1 = r0 + 8;
        #pragma unroll
        for (int nt = 0; nt < 8; nt++) {
            int col = bn + wc * 64 + nt * 8 + 2 * t4;
            float b0 = bias[col], b1 = bias[col + 1];
            float v0 = fmaxf(acc[mt][nt][0] + b0, 0.f);
            float v1 = fmaxf(acc[mt][nt][1] + b1, 0.f);
            float v2 = fmaxf(acc[mt][nt][2] + b0, 0.f);
            float v3 = fmaxf(acc[mt][nt][3] + b1, 0.f);
            u32 hi, lo;
            split_pair(v0, v1, hi, lo);
            *(u32*)&Chi[(size_t)r0 * DIM + col] = hi;
            *(u32*)&Clo[(size_t)r0 * DIM + col] = lo;
            split_pair(v2, v3, hi, lo);
            *(u32*)&Chi[(size_t)r1 * DIM + col] = hi;
            *(u32*)&Clo[(size_t)r1 * DIM + col] = lo;
        }
    }
}

// ---------------------------------------------------------------------------
// mma.sync flash attention (unchanged from R7 — verified at 2.9e-7).
// ---------------------------------------------------------------------------
#define RS    72                       // row stride (elements)
#define SMB_QHI 0
#define SMB_QLO (SMB_QHI + 128*RS*2)
#define SMB_KHI (SMB_QLO + 128*RS*2)
#define SMB_KLO (SMB_KHI + 64*RS*2)
#define SMB_VHI (SMB_KLO + 64*RS*2)
#define SMB_VLO (SMB_VHI + 64*RS*2)
#define SMB_KM  (SMB_VLO + 64*RS*2)
#define ATT_SMEM (SMB_KM + 64*4)

__global__ void __launch_bounds__(256, 2) attn_kernel(float* __restrict__ Og)
{
    extern __shared__ char smc[];
    const u32 sb = smem_u32(smc);

    const int tid  = threadIdx.x;
    const int warp = tid >> 5;
    const int lane = tid & 31;
    const int g    = lane >> 2;
    const int t4   = lane & 3;
    const int hb   = blockIdx.y;
    const int head = hb >> 2;
    const int b    = hb & 3;
    const int qt0  = blockIdx.x * 128;

    float* ksm = (float*)(smc + SMB_KM);

    {
        const uint4* qh4 = (const uint4*)g_Qhi;
        const uint4* ql4 = (const uint4*)g_Qlo;
        #pragma unroll
        for (int it = 0; it < 4; it++) {
            int c = it * 256 + tid;
            int q = c >> 3, dc = c & 7;
            size_t gi = ((size_t)(b * SEQ + qt0 + q) * DIM + head * DHEAD) / 8 + dc;
            *(uint4*)(smc + SMB_QHI + q * (RS*2) + dc * 16) = qh4[gi];
            *(uint4*)(smc + SMB_QLO + q * (RS*2) + dc * 16) = ql4[gi];
        }
    }

    const u32 aoff = (u32)((warp * 16 + (lane & 15)) * (RS*2) + ((lane >> 4) << 3) * 2);
    const u32 boff = (u32)((((lane & 7) + ((lane >> 4) << 3)) * (RS*2)) + ((((lane >> 3) & 1) << 3) * 2));
    const u32 voff = (u32)((((lane & 7) + (lane & 8)) * (RS*2)) + (((lane >> 4) << 3) * 2));

    float m0 = NEG_INF_F, m1 = NEG_INF_F, l0 = 0.f, l1 = 0.f;
    float oacc[8][4];
    #pragma unroll
    for (int j = 0; j < 8; j++)
        #pragma unroll
        for (int c = 0; c < 4; c++) oacc[j][c] = 0.f;

    for (int kt = 0; kt < SEQ / 64; kt++) {
        const int k0 = kt * 64;
        __syncthreads();

        {
            const uint4* kh4 = (const uint4*)g_Khi;
            const uint4* kl4 = (const uint4*)g_Klo;
            const uint4* vh4 = (const uint4*)g_Vhi;
            const uint4* vl4 = (const uint4*)g_Vlo;
            #pragma unroll
            for (int it = 0; it < 2; it++) {
                int c = it * 256 + tid;
                int r = c >> 3, dc = c & 7;
                size_t gi = ((size_t)(b * SEQ + k0 + r) * DIM + head * DHEAD) / 8 + dc;
                u32 so = (u32)(r * (RS*2) + dc * 16);
                *(uint4*)(smc + SMB_KHI + so) = kh4[gi];
                *(uint4*)(smc + SMB_KLO + so) = kl4[gi];
                *(uint4*)(smc + SMB_VHI + so) = vh4[gi];
                *(uint4*)(smc + SMB_VLO + so) = vl4[gi];
            }
            if (tid < 64) ksm[tid] = g_kmask[b * SEQ + k0 + tid];
        }
        __syncthreads();

        float sacc[8][4];
        #pragma unroll
        for (int j = 0; j < 8; j++)
            #pragma unroll
            for (int c = 0; c < 4; c++) sacc[j][c] = 0.f;

        #pragma unroll
        for (int kk = 0; kk < 4; kk++) {
            u32 qh[4], ql[4];
            ldm4(sb + SMB_QHI + aoff + kk * 32, qh[0], qh[1], qh[2], qh[3]);
            ldm4(sb + SMB_QLO + aoff + kk * 32, ql[0], ql[1], ql[2], ql[3]);
            #pragma unroll
            for (int nt2 = 0; nt2 < 4; nt2++) {
                u32 kh[4], kl[4];
                u32 ko = boff + nt2 * 16 * (RS*2) + kk * 32;
                ldm4(sb + SMB_KHI + ko, kh[0], kh[1], kh[2], kh[3]);
                ldm4(sb + SMB_KLO + ko, kl[0], kl[1], kl[2], kl[3]);
                mma16816(sacc[2*nt2],   qh[0], qh[1], qh[2], qh[3], kh[0], kh[1]);
                mma16816(sacc[2*nt2],   qh[0], qh[1], qh[2], qh[3], kl[0], kl[1]);
                mma16816(sacc[2*nt2],   ql[0], ql[1], ql[2], ql[3], kh[0], kh[1]);
                mma16816(sacc[2*nt2+1], qh[0], qh[1], qh[2], qh[3], kh[2], kh[3]);
                mma16816(sacc[2*nt2+1], qh[0], qh[1], qh[2], qh[3], kl[2], kl[3]);
                mma16816(sacc[2*nt2+1], ql[0], ql[1], ql[2], ql[3], kh[2], kh[3]);
            }
        }

        #pragma unroll
        for (int j = 0; j < 8; j++) {
            float km0 = ksm[8*j + 2*t4];
            float km1 = ksm[8*j + 2*t4 + 1];
            sacc[j][0] = (km0 == 0.f) ? NEG_INF_F : sacc[j][0] * 0.125f;
            sacc[j][1] = (km1 == 0.f) ? NEG_INF_F : sacc[j][1] * 0.125f;
            sacc[j][2] = (km0 == 0.f) ? NEG_INF_F : sacc[j][2] * 0.125f;
            sacc[j][3] = (km1 == 0.f) ? NEG_INF_F : sacc[j][3] * 0.125f;
        }

        float mx0 = NEG_INF_F, mx1 = NEG_INF_F;
        #pragma unroll
        for (int j = 0; j < 8; j++) {
            mx0 = fmaxf(mx0, fmaxf(sacc[j][0], sacc[j][1]));
            mx1 = fmaxf(mx1, fmaxf(sacc[j][2], sacc[j][3]));
        }
        mx0 = fmaxf(mx0, __shfl_xor_sync(0xffffffffu, mx0, 1));
        mx0 = fmaxf(mx0, __shfl_xor_sync(0xffffffffu, mx0, 2));
        mx1 = fmaxf(mx1, __shfl_xor_sync(0xffffffffu, mx1, 1));
        mx1 = fmaxf(mx1, __shfl_xor_sync(0xffffffffu, mx1, 2));

        float mn0 = fmaxf(m0, mx0), mn1 = fmaxf(m1, mx1);
        float a0 = __expf(m0 - mn0), a1 = __expf(m1 - mn1);
        m0 = mn0; m1 = mn1;

        float s0 = 0.f, s1 = 0.f;
        #pragma unroll
        for (int j = 0; j < 8; j++) {
            float p0 = __expf(sacc[j][0] - mn0);
            float p1 = __expf(sacc[j][1] - mn0);
            float p2 = __expf(sacc[j][2] - mn1);
            float p3 = __expf(sacc[j][3] - mn1);
            sacc[j][0] = p0; sacc[j][1] = p1; sacc[j][2] = p2; sacc[j][3] = p3;
            s0 += p0 + p1; s1 += p2 + p3;
        }
        s0 += __shfl_xor_sync(0xffffffffu, s0, 1);
        s0 += __shfl_xor_sync(0xffffffffu, s0, 2);
        s1 += __shfl_xor_sync(0xffffffffu, s1, 1);
        s1 += __shfl_xor_sync(0xffffffffu, s1, 2);
        l0 = l0 * a0 + s0;
        l1 = l1 * a1 + s1;

        #pragma unroll
        for (int j = 0; j < 8; j++) {
            oacc[j][0] *= a0; oacc[j][1] *= a0;
            oacc[j][2] *= a1; oacc[j][3] *= a1;
        }

        #pragma unroll
        for (int kk = 0; kk < 4; kk++) {
            u32 ph[4], pl[4];
            #pragma unroll
            for (int h = 0; h < 2; h++) {
                int j = 2 * kk + h;
                float p0 = sacc[j][0], p1 = sacc[j][1], p2 = sacc[j][2], p3 = sacc[j][3];
                u32 h01 = pack_pair(p0, p1);
                u32 h23 = pack_pair(p2, p3);
                __nv_bfloat162 b01 = *(__nv_bfloat162*)&h01;
                __nv_bfloat162 b23 = *(__nv_bfloat162*)&h23;
                ph[2*h + 0] = h01;
                ph[2*h + 1] = h23;
                pl[2*h + 0] = pack_pair(p0 - __bfloat162float(b01.x),
                                        p1 - __bfloat162float(b01.y));
                pl[2*h + 1] = pack_pair(p2 - __bfloat162float(b23.x),
                                        p3 - __bfloat162float(b23.y));
            }
            u32 A0 = ph[0], A1 = ph[1], A2 = ph[2], A3 = ph[3];
            u32 L0 = pl[0], L1 = pl[1], L2 = pl[2], L3 = pl[3];

            #pragma unroll
            for (int dt2 = 0; dt2 < 4; dt2++) {
                u32 vh[4], vl[4];
                u32 vo = voff + kk * 16 * (RS*2) + dt2 * 32;
                ldm4t(sb + SMB_VHI + vo, vh[0], vh[1], vh[2], vh[3]);
                ldm4t(sb + SMB_VLO + vo, vl[0], vl[1], vl[2], vl[3]);
                mma16816(oacc[2*dt2],   A0, A1, A2, A3, vh[0], vh[1]);
                mma16816(oacc[2*dt2],   A0, A1, A2, A3, vl[0], vl[1]);
                mma16816(oacc[2*dt2],   L0, L1, L2, L3, vh[0], vh[1]);
                mma16816(oacc[2*dt2+1], A0, A1, A2, A3, vh[2], vh[3]);
                mma16816(oacc[2*dt2+1], A0, A1, A2, A3, vl[2], vl[3]);
                mma16816(oacc[2*dt2+1], L0, L1, L2, L3, vh[2], vh[3]);
            }
        }
    }

    {
        int q0 = qt0 + warp * 16 + g;
        int q1 = q0 + 8;
        float inv0 = g_qmask[b * SEQ + q0] / l0;
        float inv1 = g_qmask[b * SEQ + q1] / l1;
        size_t base0 = (size_t)(b * SEQ + q0) * DIM + head * DHEAD;
        size_t base1 = (size_t)(b * SEQ + q1) * DIM + head * DHEAD;
        #pragma unroll
        for (int j = 0; j < 8; j++) {
            int d = 8 * j + 2 * t4;
            *(float2*)&Og[base0 + d] = make_float2(oacc[j][0] * inv0, oacc[j][1] * inv0);
            *(float2*)&Og[base1 + d] = make_float2(oacc[j][2] * inv1, oacc[j][3] * inv1);
        }
    }
}

// ---------------------------------------------------------------------------
// Residual + LayerNorm (ddof=1, eps added to std). Block per row, 128 threads.
// ---------------------------------------------------------------------------
__device__ __forceinline__ float block_sum_128(float v, float* red)
{
    #pragma unroll
    for (int o = 16; o > 0; o >>= 1) v += __shfl_xor_sync(0xffffffffu, v, o);
    int lane = threadIdx.x & 31, w = threadIdx.x >> 5;
    if (lane == 0) red[w] = v;
    __syncthreads();
    float t = red[0] + red[1] + red[2] + red[3];
    __syncthreads();
    return t;
}

__global__ void __launch_bounds__(128) ln_kernel(const float* __restrict__ queries,
                                                 const float* __restrict__ gamma,
                                                 const float* __restrict__ beta,
                                                 float* __restrict__ out)
{
    __shared__ float red[4];
    const int row = blockIdx.x;
    const int tid = threadIdx.x;
    const size_t rb = (size_t)row * DIM;

    float x[4];
    #pragma unroll
    for (int u = 0; u < 4; u++) {
        int c = tid + u * 128;
        x[u] = g_O[rb + c] + queries[rb + c];
    }
    float s = x[0] + x[1] + x[2] + x[3];
    float total = block_sum_128(s, red);
    float mean = total * (1.0f / DIM);

    float ss = 0.f;
    #pragma unroll
    for (int u = 0; u < 4; u++) { float d = x[u] - mean; ss += d * d; }
    float sstot = block_sum_128(ss, red);
    float var = sstot * (1.0f / (DIM - 1));
    float rden = 1.0f / (sqrtf(var) + LN_EPS);

    #pragma unroll
    for (int u = 0; u < 4; u++) {
        int c = tid + u * 128;
        out[rb + c] = gamma[c] * (x[u] - mean) * rden + beta[c];
    }
}

// ---------------------------------------------------------------------------
extern "C" void kernel_launch(void* const* d_in, const int* in_sizes, int n_in,
                              void* d_out, int out_size)
{
    const float* queries = (const float*)d_in[0];
    const float* keys    = (const float*)d_in[1];
    const float* values  = (const float*)d_in[2];
    const float* Wq      = (const float*)d_in[3];
    const float* bq      = (const float*)d_in[4];
    const float* Wk      = (const float*)d_in[5];
    const float* bk      = (const float*)d_in[6];
    const float* Wv      = (const float*)d_in[7];
    const float* bv      = (const float*)d_in[8];
    const float* gamma   = (const float*)d_in[9];
    const float* beta    = (const float*)d_in[10];
    float* out = (float*)d_out;

    __nv_bfloat16 *pQh, *pQl, *pKh, *pKl, *pVh, *pVl;
    float* pO;
    cudaGetSymbolAddress((void**)&pQh, g_Qhi);
    cudaGetSymbolAddress((void**)&pQl, g_Qlo);
    cudaGetSymbolAddress((void**)&pKh, g_Khi);
    cudaGetSymbolAddress((void**)&pKl, g_Klo);
    cudaGetSymbolAddress((void**)&pVh, g_Vhi);
    cudaGetSymbolAddress((void**)&pVl, g_Vlo);
    cudaGetSymbolAddress((void**)&pO,  g_O);

    cudaFuncSetAttribute(attn_kernel, cudaFuncAttributeMaxDynamicSharedMemorySize, ATT_SMEM);

    // 1. masks
    mask_kernel<<<MROWS / 8, 256>>>(keys, queries);

    // 2. projections (tensor-pipe GEMM, bf16 hi/lo 3-product)
    dim3 pgrid(DIM / 128, MROWS / 128);
    proj_mma<<<pgrid, 256>>>(queries, Wq, bq, pQh, pQl);
    proj_mma<<<pgrid, 256>>>(keys,    Wk, bk, pKh, pKl);
    proj_mma<<<pgrid, 256>>>(values,  Wv, bv, pVh, pVl);

    // 3. mma.sync flash attention
    attn_kernel<<<dim3(SEQ / 128, HB), 256, ATT_SMEM>>>(pO);

    // 4. residual + layernorm
    ln_kernel<<<MROWS, 128>>>(queries, gamma, beta, out);
}

// round 10
// speedup vs baseline: 5.6821x; 1.0804x over previous
#include <cuda_runtime.h>
#include <cuda_bf16.h>
#include <math.h>

#define BATCH 4
#define SEQ   2048
#define DIM   512
#define NHEAD 8
#define DHEAD 64
#define MROWS (BATCH*SEQ)      // 8192
#define HB    (NHEAD*BATCH)    // 32

#define NEG_INF_F (-4294967295.0f)   // -(2^32 - 1)
#define LN_EPS 1e-8f

typedef unsigned int u32;

// ---------------------------------------------------------------------------
// Scratch (no allocation allowed in kernel_launch)
// ---------------------------------------------------------------------------
// projected Q/K/V splits (attention inputs)
static __device__ __nv_bfloat16 g_Qhi[MROWS*DIM];
static __device__ __nv_bfloat16 g_Qlo[MROWS*DIM];
static __device__ __nv_bfloat16 g_Khi[MROWS*DIM];
static __device__ __nv_bfloat16 g_Klo[MROWS*DIM];
static __device__ __nv_bfloat16 g_Vhi[MROWS*DIM];
static __device__ __nv_bfloat16 g_Vlo[MROWS*DIM];
// raw input splits (projection GEMM inputs)
static __device__ __nv_bfloat16 g_Qrhi[MROWS*DIM];
static __device__ __nv_bfloat16 g_Qrlo[MROWS*DIM];
static __device__ __nv_bfloat16 g_Krhi[MROWS*DIM];
static __device__ __nv_bfloat16 g_Krlo[MROWS*DIM];
static __device__ __nv_bfloat16 g_Vrhi[MROWS*DIM];
static __device__ __nv_bfloat16 g_Vrlo[MROWS*DIM];
// weight splits
static __device__ __nv_bfloat16 g_Wqhi[DIM*DIM];
static __device__ __nv_bfloat16 g_Wqlo[DIM*DIM];
static __device__ __nv_bfloat16 g_Wkhi[DIM*DIM];
static __device__ __nv_bfloat16 g_Wklo[DIM*DIM];
static __device__ __nv_bfloat16 g_Wvhi[DIM*DIM];
static __device__ __nv_bfloat16 g_Wvlo[DIM*DIM];

static __device__ float g_O[MROWS*DIM];
static __device__ float g_kmask[MROWS];
static __device__ float g_qmask[MROWS];

// ---------------------------------------------------------------------------
// helpers
// ---------------------------------------------------------------------------
__device__ __forceinline__ u32 smem_u32(const void* p) {
    u32 a;
    asm("{ .reg .u64 t; cvta.to.shared.u64 t, %1; cvt.u32.u64 %0, t; }" : "=r"(a) : "l"(p));
    return a;
}
__device__ __forceinline__ void ldm4(u32 addr, u32& r0, u32& r1, u32& r2, u32& r3) {
    asm volatile("ldmatrix.sync.aligned.m8n8.x4.shared.b16 {%0,%1,%2,%3}, [%4];"
                 : "=r"(r0), "=r"(r1), "=r"(r2), "=r"(r3) : "r"(addr));
}
__device__ __forceinline__ void ldm4t(u32 addr, u32& r0, u32& r1, u32& r2, u32& r3) {
    asm volatile("ldmatrix.sync.aligned.m8n8.x4.trans.shared.b16 {%0,%1,%2,%3}, [%4];"
                 : "=r"(r0), "=r"(r1), "=r"(r2), "=r"(r3) : "r"(addr));
}
__device__ __forceinline__ void mma16816(float d[4], u32 a0, u32 a1, u32 a2, u32 a3,
                                         u32 b0, u32 b1) {
    asm volatile("mma.sync.aligned.m16n8k16.row.col.f32.bf16.bf16.f32 "
                 "{%0,%1,%2,%3}, {%4,%5,%6,%7}, {%8,%9}, {%0,%1,%2,%3};"
                 : "+f"(d[0]), "+f"(d[1]), "+f"(d[2]), "+f"(d[3])
                 : "r"(a0), "r"(a1), "r"(a2), "r"(a3), "r"(b0), "r"(b1));
}
__device__ __forceinline__ u32 pack_pair(float lo, float hi) {
    __nv_bfloat162 t = __halves2bfloat162(__float2bfloat16(lo), __float2bfloat16(hi));
    return *(u32*)&t;
}
__device__ __forceinline__ void split_pair(float v0, float v1, u32& hi, u32& lo) {
    __nv_bfloat16 h0 = __float2bfloat16(v0);
    __nv_bfloat16 h1 = __float2bfloat16(v1);
    __nv_bfloat162 hh = __halves2bfloat162(h0, h1);
    __nv_bfloat162 ll = __halves2bfloat162(__float2bfloat16(v0 - __bfloat162float(h0)),
                                           __float2bfloat16(v1 - __bfloat162float(h1)));
    hi = *(u32*)&hh;
    lo = *(u32*)&ll;
}
__device__ __forceinline__ void cp16(u32 dst, const void* src) {
    asm volatile("cp.async.cg.shared.global [%0], [%1], 16;" :: "r"(dst), "l"(src));
}
#define CP_COMMIT() asm volatile("cp.async.commit_group;" ::: "memory")
#define CP_WAIT1()  asm volatile("cp.async.wait_group 1;" ::: "memory")
#define CP_WAIT0()  asm volatile("cp.async.wait_group 0;" ::: "memory")

// ---------------------------------------------------------------------------
// prep: masks + bf16 hi/lo split of raw q/k/v. Warp per row.
// ---------------------------------------------------------------------------
__global__ void __launch_bounds__(256) prep_kernel(const float* __restrict__ q,
                                                   const float* __restrict__ k,
                                                   const float* __restrict__ v)
{
    int warp = threadIdx.x >> 5;
    int lane = threadIdx.x & 31;
    int row  = blockIdx.x * 8 + warp;
    const float2* qr = (const float2*)(q + (size_t)row * DIM);
    const float2* kr = (const float2*)(k + (size_t)row * DIM);
    const float2* vr = (const float2*)(v + (size_t)row * DIM);
    float sq = 0.f, sk = 0.f;
    #pragma unroll
    for (int it = 0; it < 8; it++) {
        int p = it * 32 + lane;                 // pair index 0..255
        size_t o = (size_t)row * 256 + p;
        u32 hi, lo;
        float2 x = qr[p]; sq += x.x + x.y;
        split_pair(x.x, x.y, hi, lo);
        ((u32*)g_Qrhi)[o] = hi; ((u32*)g_Qrlo)[o] = lo;
        x = kr[p]; sk += x.x + x.y;
        split_pair(x.x, x.y, hi, lo);
        ((u32*)g_Krhi)[o] = hi; ((u32*)g_Krlo)[o] = lo;
        x = vr[p];
        split_pair(x.x, x.y, hi, lo);
        ((u32*)g_Vrhi)[o] = hi; ((u32*)g_Vrlo)[o] = lo;
    }
    #pragma unroll
    for (int o = 16; o > 0; o >>= 1) {
        sq += __shfl_xor_sync(0xffffffffu, sq, o);
        sk += __shfl_xor_sync(0xffffffffu, sk, o);
    }
    if (lane == 0) {
        g_kmask[row] = (sk != 0.0f) ? 1.0f : 0.0f;
        g_qmask[row] = (sq != 0.0f) ? 1.0f : 0.0f;
    }
}

// ---------------------------------------------------------------------------
// weight split: block per row (512 blocks x 256 thr, 1 pair/thread)
// ---------------------------------------------------------------------------
__global__ void __launch_bounds__(256) wsplit_kernel(const float* __restrict__ W,
                                                     __nv_bfloat16* __restrict__ Whi,
                                                     __nv_bfloat16* __restrict__ Wlo)
{
    int row = blockIdx.x, t = threadIdx.x;
    const float2* wr = (const float2*)(W + (size_t)row * DIM);
    float2 x = wr[t];
    u32 hi, lo;
    split_pair(x.x, x.y, hi, lo);
    ((u32*)Whi)[(size_t)row * 256 + t] = hi;
    ((u32*)Wlo)[(size_t)row * 256 + t] = lo;
}

// ---------------------------------------------------------------------------
// Projection GEMM, pure bf16, cp.async 2-stage pipeline.
// CTA 128x128, 8 warps (4 row x 2 col), warp tile 32x64, k-chunks of 32.
// ---------------------------------------------------------------------------
#define PA_RS 40
#define PW_RS 136
#define P_AH 0
#define P_AL (128*PA_RS*2)            // 10240
#define P_WH (2*128*PA_RS*2)          // 20480
#define P_WL (P_WH + 32*PW_RS*2)      // 29184
#define P_STAGE (P_WL + 32*PW_RS*2)   // 37888
#define PROJ_SMEM (2*P_STAGE)         // 75776

__global__ void __launch_bounds__(256, 2) proj_mma(const __nv_bfloat16* __restrict__ Ahi,
                                                   const __nv_bfloat16* __restrict__ Alo,
                                                   const __nv_bfloat16* __restrict__ Whi,
                                                   const __nv_bfloat16* __restrict__ Wlo,
                                                   const float* __restrict__ bias,
                                                   __nv_bfloat16* __restrict__ Chi,
                                                   __nv_bfloat16* __restrict__ Clo)
{
    extern __shared__ char smc[];
    const u32 sb = smem_u32(smc);

    const int tid  = threadIdx.x;
    const int warp = tid >> 5;
    const int lane = tid & 31;
    const int g    = lane >> 2;
    const int t4   = lane & 3;
    const int wr   = warp & 3;
    const int wc   = warp >> 2;
    const int bm   = blockIdx.y * 128;
    const int bn   = blockIdx.x * 128;

    const uint4* ah4 = (const uint4*)Ahi;
    const uint4* al4 = (const uint4*)Alo;
    const uint4* wh4 = (const uint4*)Whi;
    const uint4* wl4 = (const uint4*)Wlo;

    auto load_chunk = [&](int kc, int st) {
        int k0 = kc * 32;
        u32 base = sb + st * P_STAGE;
        #pragma unroll
        for (int it = 0; it < 2; it++) {
            int c = it * 256 + tid;              // 0..511
            {   // A: r = c>>2 (0..127), granule c&3
                int r = c >> 2, gc = c & 3;
                size_t gi = ((size_t)(bm + r) * DIM + k0) / 8 + gc;
                u32 so = (u32)(r * PA_RS * 2 + gc * 16);
                cp16(base + P_AH + so, ah4 + gi);
                cp16(base + P_AL + so, al4 + gi);
            }
            {   // W: r = c>>4 (0..31), granule c&15
                int r = c >> 4, gc = c & 15;
                size_t gi = ((size_t)(k0 + r) * DIM + bn) / 8 + gc;
                u32 so = (u32)(r * PW_RS * 2 + gc * 16);
                cp16(base + P_WH + so, wh4 + gi);
                cp16(base + P_WL + so, wl4 + gi);
            }
        }
    };

    // ldmatrix lane offsets (bytes, stage-relative)
    const u32 aoff = (u32)(((wr * 32 + (lane & 15)) * PA_RS + ((lane >> 4) << 3)) * 2);
    const u32 woff = (u32)(((((lane & 7) + (lane & 8)) * PW_RS) +
                            wc * 64 + (((lane >> 4) << 3))) * 2);

    float acc[2][8][4];
    #pragma unroll
    for (int mt = 0; mt < 2; mt++)
        #pragma unroll
        for (int nt = 0; nt < 8; nt++)
            #pragma unroll
            for (int c = 0; c < 4; c++) acc[mt][nt][c] = 0.f;

    load_chunk(0, 0);
    CP_COMMIT();

    for (int kc = 0; kc < DIM / 32; kc++) {
        const int st = kc & 1;
        if (kc + 1 < DIM / 32) {
            load_chunk(kc + 1, st ^ 1);
            CP_COMMIT();
            CP_WAIT1();
        } else {
            CP_WAIT0();
        }
        __syncthreads();

        const u32 pb  = sb + st * P_STAGE;
        #pragma unroll
        for (int kk = 0; kk < 2; kk++) {
            u32 ah[2][4], al[2][4];
            #pragma unroll
            for (int mt = 0; mt < 2; mt++) {
                u32 ao = aoff + (u32)((mt * 16 * PA_RS + kk * 16) * 2);
                ldm4(pb + P_AH + ao, ah[mt][0], ah[mt][1], ah[mt][2], ah[mt][3]);
                ldm4(pb + P_AL + ao, al[mt][0], al[mt][1], al[mt][2], al[mt][3]);
            }
            #pragma unroll
            for (int nt2 = 0; nt2 < 4; nt2++) {
                u32 wh[4], wl[4];
                u32 wo = woff + (u32)((kk * 16 * PW_RS + nt2 * 16) * 2);
                ldm4t(pb + P_WH + wo, wh[0], wh[1], wh[2], wh[3]);
                ldm4t(pb + P_WL + wo, wl[0], wl[1], wl[2], wl[3]);
                #pragma unroll
                for (int mt = 0; mt < 2; mt++) {
                    mma16816(acc[mt][2*nt2],   ah[mt][0], ah[mt][1], ah[mt][2], ah[mt][3], wh[0], wh[1]);
                    mma16816(acc[mt][2*nt2],   ah[mt][0], ah[mt][1], ah[mt][2], ah[mt][3], wl[0], wl[1]);
                    mma16816(acc[mt][2*nt2],   al[mt][0], al[mt][1], al[mt][2], al[mt][3], wh[0], wh[1]);
                    mma16816(acc[mt][2*nt2+1], ah[mt][0], ah[mt][1], ah[mt][2], ah[mt][3], wh[2], wh[3]);
                    mma16816(acc[mt][2*nt2+1], ah[mt][0], ah[mt][1], ah[mt][2], ah[mt][3], wl[2], wl[3]);
                    mma16816(acc[mt][2*nt2+1], al[mt][0], al[mt][1], al[mt][2], al[mt][3], wh[2], wh[3]);
                }
            }
        }
        __syncthreads();
    }

    // ---- epilogue: bias + relu, split to bf16 hi/lo ----
    #pragma unroll
    for (int mt = 0; mt < 2; mt++) {
        int r0 = bm + wr * 32 + mt * 16 + g;
        int r1 = r0 + 8;
        #pragma unroll
        for (int nt = 0; nt < 8; nt++) {
            int col = bn + wc * 64 + nt * 8 + 2 * t4;
            float b0 = bias[col], b1 = bias[col + 1];
            float v0 = fmaxf(acc[mt][nt][0] + b0, 0.f);
            float v1 = fmaxf(acc[mt][nt][1] + b1, 0.f);
            float v2 = fmaxf(acc[mt][nt][2] + b0, 0.f);
            float v3 = fmaxf(acc[mt][nt][3] + b1, 0.f);
            u32 hi, lo;
            split_pair(v0, v1, hi, lo);
            *(u32*)&Chi[(size_t)r0 * DIM + col] = hi;
            *(u32*)&Clo[(size_t)r0 * DIM + col] = lo;
            split_pair(v2, v3, hi, lo);
            *(u32*)&Chi[(size_t)r1 * DIM + col] = hi;
            *(u32*)&Clo[(size_t)r1 * DIM + col] = lo;
        }
    }
}

// ---------------------------------------------------------------------------
// mma.sync flash attention with cp.async 2-stage K/V pipeline.
// CTA: 256 thr (8 warps), 128 q-rows x one hb; key tiles of 64.
// ---------------------------------------------------------------------------
#define RS    72                       // row stride (elements)
#define KVB   (64*RS*2)                // 9216 per array
#define KV_STAGE (4*KVB)               // 36864 (K hi/lo, V hi/lo)
#define SMB_QHI 0
#define SMB_QLO (128*RS*2)             // 18432
#define SMB_KV  (2*128*RS*2)           // 36864
#define ATT_SMEM (SMB_KV + 2*KV_STAGE) // 110592

__global__ void __launch_bounds__(256, 2) attn_kernel(float* __restrict__ Og)
{
    extern __shared__ char smc[];
    const u32 sb = smem_u32(smc);

    const int tid  = threadIdx.x;
    const int warp = tid >> 5;
    const int lane = tid & 31;
    const int g    = lane >> 2;
    const int t4   = lane & 3;
    const int hb   = blockIdx.y;
    const int head = hb >> 2;
    const int b    = hb & 3;
    const int qt0  = blockIdx.x * 128;

    // ---- Q tile (plain stores; covered by first __syncthreads) ----
    {
        const uint4* qh4 = (const uint4*)g_Qhi;
        const uint4* ql4 = (const uint4*)g_Qlo;
        #pragma unroll
        for (int it = 0; it < 4; it++) {
            int c = it * 256 + tid;
            int q = c >> 3, dc = c & 7;
            size_t gi = ((size_t)(b * SEQ + qt0 + q) * DIM + head * DHEAD) / 8 + dc;
            *(uint4*)(smc + SMB_QHI + q * (RS*2) + dc * 16) = qh4[gi];
            *(uint4*)(smc + SMB_QLO + q * (RS*2) + dc * 16) = ql4[gi];
        }
    }

    const uint4* kh4 = (const uint4*)g_Khi;
    const uint4* kl4 = (const uint4*)g_Klo;
    const uint4* vh4 = (const uint4*)g_Vhi;
    const uint4* vl4 = (const uint4*)g_Vlo;

    auto load_tile = [&](int kt, int st) {
        int k0 = kt * 64;
        u32 base = sb + SMB_KV + st * KV_STAGE;
        #pragma unroll
        for (int it = 0; it < 2; it++) {
            int c = it * 256 + tid;      // 0..511
            int r = c >> 3, dc = c & 7;
            size_t gi = ((size_t)(b * SEQ + k0 + r) * DIM + head * DHEAD) / 8 + dc;
            u32 so = (u32)(r * (RS*2) + dc * 16);
            cp16(base + 0*KVB + so, kh4 + gi);
            cp16(base + 1*KVB + so, kl4 + gi);
            cp16(base + 2*KVB + so, vh4 + gi);
            cp16(base + 3*KVB + so, vl4 + gi);
        }
    };

    const u32 aoff = (u32)((warp * 16 + (lane & 15)) * (RS*2) + ((lane >> 4) << 3) * 2);
    const u32 boff = (u32)((((lane & 7) + ((lane >> 4) << 3)) * (RS*2)) + ((((lane >> 3) & 1) << 3) * 2));
    const u32 voff = (u32)((((lane & 7) + (lane & 8)) * (RS*2)) + (((lane >> 4) << 3) * 2));

    float m0 = NEG_INF_F, m1 = NEG_INF_F, l0 = 0.f, l1 = 0.f;
    float oacc[8][4];
    #pragma unroll
    for (int j = 0; j < 8; j++)
        #pragma unroll
        for (int c = 0; c < 4; c++) oacc[j][c] = 0.f;

    load_tile(0, 0);
    CP_COMMIT();

    for (int kt = 0; kt < SEQ / 64; kt++) {
        const int st = kt & 1;
        const int k0 = kt * 64;

        // key-mask for my 8 columns (global loads, L2-resident after first pass)
        float km[8][2];
        #pragma unroll
        for (int j = 0; j < 8; j++) {
            km[j][0] = g_kmask[b * SEQ + k0 + 8*j + 2*t4];
            km[j][1] = g_kmask[b * SEQ + k0 + 8*j + 2*t4 + 1];
        }

        if (kt + 1 < SEQ / 64) {
            load_tile(kt + 1, st ^ 1);
            CP_COMMIT();
            CP_WAIT1();
        } else {
            CP_WAIT0();
        }
        __syncthreads();

        const u32 kb = sb + SMB_KV + st * KV_STAGE;

        // ---- GEMM1: S[16x64] = Q K^T (hi*hi + hi*lo + lo*hi) ----
        float sacc[8][4];
        #pragma unroll
        for (int j = 0; j < 8; j++)
            #pragma unroll
            for (int c = 0; c < 4; c++) sacc[j][c] = 0.f;

        #pragma unroll
        for (int kk = 0; kk < 4; kk++) {
            u32 qh[4], ql[4];
            ldm4(sb + SMB_QHI + aoff + kk * 32, qh[0], qh[1], qh[2], qh[3]);
            ldm4(sb + SMB_QLO + aoff + kk * 32, ql[0], ql[1], ql[2], ql[3]);
            #pragma unroll
            for (int nt2 = 0; nt2 < 4; nt2++) {
                u32 kh[4], kl[4];
                u32 ko = boff + nt2 * 16 * (RS*2) + kk * 32;
                ldm4(kb + 0*KVB + ko, kh[0], kh[1], kh[2], kh[3]);
                ldm4(kb + 1*KVB + ko, kl[0], kl[1], kl[2], kl[3]);
                mma16816(sacc[2*nt2],   qh[0], qh[1], qh[2], qh[3], kh[0], kh[1]);
                mma16816(sacc[2*nt2],   qh[0], qh[1], qh[2], qh[3], kl[0], kl[1]);
                mma16816(sacc[2*nt2],   ql[0], ql[1], ql[2], ql[3], kh[0], kh[1]);
                mma16816(sacc[2*nt2+1], qh[0], qh[1], qh[2], qh[3], kh[2], kh[3]);
                mma16816(sacc[2*nt2+1], qh[0], qh[1], qh[2], qh[3], kl[2], kl[3]);
                mma16816(sacc[2*nt2+1], ql[0], ql[1], ql[2], ql[3], kh[2], kh[3]);
            }
        }

        // ---- scale + key mask ----
        #pragma unroll
        for (int j = 0; j < 8; j++) {
            sacc[j][0] = (km[j][0] == 0.f) ? NEG_INF_F : sacc[j][0] * 0.125f;
            sacc[j][1] = (km[j][1] == 0.f) ? NEG_INF_F : sacc[j][1] * 0.125f;
            sacc[j][2] = (km[j][0] == 0.f) ? NEG_INF_F : sacc[j][2] * 0.125f;
            sacc[j][3] = (km[j][1] == 0.f) ? NEG_INF_F : sacc[j][3] * 0.125f;
        }

        // ---- online softmax (rows g and g+8, warp-local) ----
        float mx0 = NEG_INF_F, mx1 = NEG_INF_F;
        #pragma unroll
        for (int j = 0; j < 8; j++) {
            mx0 = fmaxf(mx0, fmaxf(sacc[j][0], sacc[j][1]));
            mx1 = fmaxf(mx1, fmaxf(sacc[j][2], sacc[j][3]));
        }
        mx0 = fmaxf(mx0, __shfl_xor_sync(0xffffffffu, mx0, 1));
        mx0 = fmaxf(mx0, __shfl_xor_sync(0xffffffffu, mx0, 2));
        mx1 = fmaxf(mx1, __shfl_xor_sync(0xffffffffu, mx1, 1));
        mx1 = fmaxf(mx1, __shfl_xor_sync(0xffffffffu, mx1, 2));

        float mn0 = fmaxf(m0, mx0), mn1 = fmaxf(m1, mx1);
        float a0 = __expf(m0 - mn0), a1 = __expf(m1 - mn1);
        m0 = mn0; m1 = mn1;

        float s0 = 0.f, s1 = 0.f;
        #pragma unroll
        for (int j = 0; j < 8; j++) {
            float p0 = __expf(sacc[j][0] - mn0);
            float p1 = __expf(sacc[j][1] - mn0);
            float p2 = __expf(sacc[j][2] - mn1);
            float p3 = __expf(sacc[j][3] - mn1);
            sacc[j][0] = p0; sacc[j][1] = p1; sacc[j][2] = p2; sacc[j][3] = p3;
            s0 += p0 + p1; s1 += p2 + p3;
        }
        s0 += __shfl_xor_sync(0xffffffffu, s0, 1);
        s0 += __shfl_xor_sync(0xffffffffu, s0, 2);
        s1 += __shfl_xor_sync(0xffffffffu, s1, 1);
        s1 += __shfl_xor_sync(0xffffffffu, s1, 2);
        l0 = l0 * a0 + s0;
        l1 = l1 * a1 + s1;

        #pragma unroll
        for (int j = 0; j < 8; j++) {
            oacc[j][0] *= a0; oacc[j][1] *= a0;
            oacc[j][2] *= a1; oacc[j][3] *= a1;
        }

        // ---- GEMM2: O += P V (hi*hi + hi*lo + lo*hi) ----
        #pragma unroll
        for (int kk = 0; kk < 4; kk++) {
            u32 ph[4], pl[4];
            #pragma unroll
            for (int h = 0; h < 2; h++) {
                int j = 2 * kk + h;
                float p0 = sacc[j][0], p1 = sacc[j][1], p2 = sacc[j][2], p3 = sacc[j][3];
                u32 h01 = pack_pair(p0, p1);
                u32 h23 = pack_pair(p2, p3);
                __nv_bfloat162 b01 = *(__nv_bfloat162*)&h01;
                __nv_bfloat162 b23 = *(__nv_bfloat162*)&h23;
                ph[2*h + 0] = h01;
                ph[2*h + 1] = h23;
                pl[2*h + 0] = pack_pair(p0 - __bfloat162float(b01.x),
                                        p1 - __bfloat162float(b01.y));
                pl[2*h + 1] = pack_pair(p2 - __bfloat162float(b23.x),
                                        p3 - __bfloat162float(b23.y));
            }
            u32 A0 = ph[0], A1 = ph[1], A2 = ph[2], A3 = ph[3];
            u32 L0 = pl[0], L1 = pl[1], L2 = pl[2], L3 = pl[3];

            #pragma unroll
            for (int dt2 = 0; dt2 < 4; dt2++) {
                u32 vh[4], vl[4];
                u32 vo = voff + kk * 16 * (RS*2) + dt2 * 32;
                ldm4t(kb + 2*KVB + vo, vh[0], vh[1], vh[2], vh[3]);
                ldm4t(kb + 3*KVB + vo, vl[0], vl[1], vl[2], vl[3]);
                mma16816(oacc[2*dt2],   A0, A1, A2, A3, vh[0], vh[1]);
                mma16816(oacc[2*dt2],   A0, A1, A2, A3, vl[0], vl[1]);
                mma16816(oacc[2*dt2],   L0, L1, L2, L3, vh[0], vh[1]);
                mma16816(oacc[2*dt2+1], A0, A1, A2, A3, vh[2], vh[3]);
                mma16816(oacc[2*dt2+1], A0, A1, A2, A3, vl[2], vl[3]);
                mma16816(oacc[2*dt2+1], L0, L1, L2, L3, vh[2], vh[3]);
            }
        }
        __syncthreads();   // stage st reads done before next-iter loads overwrite it
    }

    // ---- epilogue: normalize, query mask, write ----
    {
        int q0 = qt0 + warp * 16 + g;
        int q1 = q0 + 8;
        float inv0 = g_qmask[b * SEQ + q0] / l0;
        float inv1 = g_qmask[b * SEQ + q1] / l1;
        size_t base0 = (size_t)(b * SEQ + q0) * DIM + head * DHEAD;
        size_t base1 = (size_t)(b * SEQ + q1) * DIM + head * DHEAD;
        #pragma unroll
        for (int j = 0; j < 8; j++) {
            int d = 8 * j + 2 * t4;
            *(float2*)&Og[base0 + d] = make_float2(oacc[j][0] * inv0, oacc[j][1] * inv0);
            *(float2*)&Og[base1 + d] = make_float2(oacc[j][2] * inv1, oacc[j][3] * inv1);
        }
    }
}

// ---------------------------------------------------------------------------
// Residual + LayerNorm (ddof=1, eps added to std). Block per row, 128 threads.
// ---------------------------------------------------------------------------
__device__ __forceinline__ float block_sum_128(float v, float* red)
{
    #pragma unroll
    for (int o = 16; o > 0; o >>= 1) v += __shfl_xor_sync(0xffffffffu, v, o);
    int lane = threadIdx.x & 31, w = threadIdx.x >> 5;
    if (lane == 0) red[w] = v;
    __syncthreads();
    float t = red[0] + red[1] + red[2] + red[3];
    __syncthreads();
    return t;
}

__global__ void __launch_bounds__(128) ln_kernel(const float* __restrict__ queries,
                                                 const float* __restrict__ gamma,
                                                 const float* __restrict__ beta,
                                                 float* __restrict__ out)
{
    __shared__ float red[4];
    const int row = blockIdx.x;
    const int tid = threadIdx.x;
    const size_t rb = (size_t)row * DIM;

    float x[4];
    #pragma unroll
    for (int u = 0; u < 4; u++) {
        int c = tid + u * 128;
        x[u] = g_O[rb + c] + queries[rb + c];
    }
    float s = x[0] + x[1] + x[2] + x[3];
    float total = block_sum_128(s, red);
    float mean = total * (1.0f / DIM);

    float ss = 0.f;
    #pragma unroll
    for (int u = 0; u < 4; u++) { float d = x[u] - mean; ss += d * d; }
    float sstot = block_sum_128(ss, red);
    float var = sstot * (1.0f / (DIM - 1));
    float rden = 1.0f / (sqrtf(var) + LN_EPS);

    #pragma unroll
    for (int u = 0; u < 4; u++) {
        int c = tid + u * 128;
        out[rb + c] = gamma[c] * (x[u] - mean) * rden + beta[c];
    }
}

// ---------------------------------------------------------------------------
extern "C" void kernel_launch(void* const* d_in, const int* in_sizes, int n_in,
                              void* d_out, int out_size)
{
    const float* queries = (const float*)d_in[0];
    const float* keys    = (const float*)d_in[1];
    const float* values  = (const float*)d_in[2];
    const float* Wq      = (const float*)d_in[3];
    const float* bq      = (const float*)d_in[4];
    const float* Wk      = (const float*)d_in[5];
    const float* bk      = (const float*)d_in[6];
    const float* Wv      = (const float*)d_in[7];
    const float* bv      = (const float*)d_in[8];
    const float* gamma   = (const float*)d_in[9];
    const float* beta    = (const float*)d_in[10];
    float* out = (float*)d_out;

    __nv_bfloat16 *pQh, *pQl, *pKh, *pKl, *pVh, *pVl;
    __nv_bfloat16 *pQrh, *pQrl, *pKrh, *pKrl, *pVrh, *pVrl;
    __nv_bfloat16 *pWqh, *pWql, *pWkh, *pWkl, *pWvh, *pWvl;
    float* pO;
    cudaGetSymbolAddress((void**)&pQh, g_Qhi);
    cudaGetSymbolAddress((void**)&pQl, g_Qlo);
    cudaGetSymbolAddress((void**)&pKh, g_Khi);
    cudaGetSymbolAddress((void**)&pKl, g_Klo);
    cudaGetSymbolAddress((void**)&pVh, g_Vhi);
    cudaGetSymbolAddress((void**)&pVl, g_Vlo);
    cudaGetSymbolAddress((void**)&pQrh, g_Qrhi);
    cudaGetSymbolAddress((void**)&pQrl, g_Qrlo);
    cudaGetSymbolAddress((void**)&pKrh, g_Krhi);
    cudaGetSymbolAddress((void**)&pKrl, g_Krlo);
    cudaGetSymbolAddress((void**)&pVrh, g_Vrhi);
    cudaGetSymbolAddress((void**)&pVrl, g_Vrlo);
    cudaGetSymbolAddress((void**)&pWqh, g_Wqhi);
    cudaGetSymbolAddress((void**)&pWql, g_Wqlo);
    cudaGetSymbolAddress((void**)&pWkh, g_Wkhi);
    cudaGetSymbolAddress((void**)&pWkl, g_Wklo);
    cudaGetSymbolAddress((void**)&pWvh, g_Wvhi);
    cudaGetSymbolAddress((void**)&pWvl, g_Wvlo);
    cudaGetSymbolAddress((void**)&pO,  g_O);

    cudaFuncSetAttribute(attn_kernel, cudaFuncAttributeMaxDynamicSharedMemorySize, ATT_SMEM);
    cudaFuncSetAttribute(proj_mma, cudaFuncAttributeMaxDynamicSharedMemorySize, PROJ_SMEM);

    // 1. masks + raw input splits
    prep_kernel<<<MROWS / 8, 256>>>(queries, keys, values);
    wsplit_kernel<<<DIM, 256>>>(Wq, pWqh, pWql);
    wsplit_kernel<<<DIM, 256>>>(Wk, pWkh, pWkl);
    wsplit_kernel<<<DIM, 256>>>(Wv, pWvh, pWvl);

    // 2. projections (tensor pipe, cp.async pipelined)
    dim3 pgrid(DIM / 128, MROWS / 128);
    proj_mma<<<pgrid, 256, PROJ_SMEM>>>(pQrh, pQrl, pWqh, pWql, bq, pQh, pQl);
    proj_mma<<<pgrid, 256, PROJ_SMEM>>>(pKrh, pKrl, pWkh, pWkl, bk, pKh, pKl);
    proj_mma<<<pgrid, 256, PROJ_SMEM>>>(pVrh, pVrl, pWvh, pWvl, bv, pVh, pVl);

    // 3. mma.sync flash attention (cp.async pipelined)
    attn_kernel<<<dim3(SEQ / 128, HB), 256, ATT_SMEM>>>(pO);

    // 4. residual + layernorm
    ln_kernel<<<MROWS, 128>>>(queries, gamma, beta, out);
}

// round 13
// speedup vs baseline: 5.9373x; 1.0449x over previous
#include <cuda_runtime.h>
#include <cuda_bf16.h>
#include <math.h>

#define BATCH 4
#define SEQ   2048
#define DIM   512
#define NHEAD 8
#define DHEAD 64
#define MROWS (BATCH*SEQ)      // 8192
#define HB    (NHEAD*BATCH)    // 32

#define NEG_INF_F (-4294967295.0f)   // -(2^32 - 1)
#define LOG2E     1.4426950408889634f
#define QSCALE    (0.125f * LOG2E)   // folded into Q projection epilogue
#define LN_EPS 1e-8f

typedef unsigned int u32;

// ---------------------------------------------------------------------------
// Scratch (no allocation allowed in kernel_launch)
// ---------------------------------------------------------------------------
static __device__ __nv_bfloat16 g_Qhi[MROWS*DIM];
static __device__ __nv_bfloat16 g_Qlo[MROWS*DIM];
static __device__ __nv_bfloat16 g_Khi[MROWS*DIM];
static __device__ __nv_bfloat16 g_Klo[MROWS*DIM];
static __device__ __nv_bfloat16 g_Vhi[MROWS*DIM];
static __device__ __nv_bfloat16 g_Vlo[MROWS*DIM];
static __device__ __nv_bfloat16 g_Qrhi[MROWS*DIM];
static __device__ __nv_bfloat16 g_Qrlo[MROWS*DIM];
static __device__ __nv_bfloat16 g_Krhi[MROWS*DIM];
static __device__ __nv_bfloat16 g_Krlo[MROWS*DIM];
static __device__ __nv_bfloat16 g_Vrhi[MROWS*DIM];
static __device__ __nv_bfloat16 g_Vrlo[MROWS*DIM];
static __device__ __nv_bfloat16 g_Wqhi[DIM*DIM];
static __device__ __nv_bfloat16 g_Wqlo[DIM*DIM];
static __device__ __nv_bfloat16 g_Wkhi[DIM*DIM];
static __device__ __nv_bfloat16 g_Wklo[DIM*DIM];
static __device__ __nv_bfloat16 g_Wvhi[DIM*DIM];
static __device__ __nv_bfloat16 g_Wvlo[DIM*DIM];

static __device__ float g_O[MROWS*DIM];
static __device__ float g_kbias[MROWS];   // 0 or NEG_INF*log2e (additive, log2 domain)
static __device__ float g_qmask[MROWS];

// ---------------------------------------------------------------------------
// helpers
// ---------------------------------------------------------------------------
__device__ __forceinline__ u32 smem_u32(const void* p) {
    u32 a;
    asm("{ .reg .u64 t; cvta.to.shared.u64 t, %1; cvt.u32.u64 %0, t; }" : "=r"(a) : "l"(p));
    return a;
}
__device__ __forceinline__ void ldm4(u32 addr, u32& r0, u32& r1, u32& r2, u32& r3) {
    asm volatile("ldmatrix.sync.aligned.m8n8.x4.shared.b16 {%0,%1,%2,%3}, [%4];"
                 : "=r"(r0), "=r"(r1), "=r"(r2), "=r"(r3) : "r"(addr));
}
__device__ __forceinline__ void ldm4t(u32 addr, u32& r0, u32& r1, u32& r2, u32& r3) {
    asm volatile("ldmatrix.sync.aligned.m8n8.x4.trans.shared.b16 {%0,%1,%2,%3}, [%4];"
                 : "=r"(r0), "=r"(r1), "=r"(r2), "=r"(r3) : "r"(addr));
}
__device__ __forceinline__ void mma16816(float d[4], u32 a0, u32 a1, u32 a2, u32 a3,
                                         u32 b0, u32 b1) {
    asm volatile("mma.sync.aligned.m16n8k16.row.col.f32.bf16.bf16.f32 "
                 "{%0,%1,%2,%3}, {%4,%5,%6,%7}, {%8,%9}, {%0,%1,%2,%3};"
                 : "+f"(d[0]), "+f"(d[1]), "+f"(d[2]), "+f"(d[3])
                 : "r"(a0), "r"(a1), "r"(a2), "r"(a3), "r"(b0), "r"(b1));
}
__device__ __forceinline__ u32 pack_pair(float lo, float hi) {
    __nv_bfloat162 t = __halves2bfloat162(__float2bfloat16(lo), __float2bfloat16(hi));
    return *(u32*)&t;
}
__device__ __forceinline__ void split_pair(float v0, float v1, u32& hi, u32& lo) {
    __nv_bfloat16 h0 = __float2bfloat16(v0);
    __nv_bfloat16 h1 = __float2bfloat16(v1);
    __nv_bfloat162 hh = __halves2bfloat162(h0, h1);
    __nv_bfloat162 ll = __halves2bfloat162(__float2bfloat16(v0 - __bfloat162float(h0)),
                                           __float2bfloat16(v1 - __bfloat162float(h1)));
    hi = *(u32*)&hh;
    lo = *(u32*)&ll;
}
__device__ __forceinline__ void cp16(u32 dst, const void* src) {
    asm volatile("cp.async.cg.shared.global [%0], [%1], 16;" :: "r"(dst), "l"(src));
}
#define CP_COMMIT() asm volatile("cp.async.commit_group;" ::: "memory")
#define CP_WAIT1()  asm volatile("cp.async.wait_group 1;" ::: "memory")
#define CP_WAIT0()  asm volatile("cp.async.wait_group 0;" ::: "memory")
__device__ __forceinline__ float ex2(float x) {
    float r;
    asm("ex2.approx.f32 %0, %1;" : "=f"(r) : "f"(x));
    return r;
}

// ---------------------------------------------------------------------------
// prep_all: blocks [0,1024): masks/kbias + input splits (warp per row)
//           blocks [1024,2560): weight splits (block per row, 3 matrices)
// ---------------------------------------------------------------------------
__global__ void __launch_bounds__(256) prep_all(const float* __restrict__ q,
                                                const float* __restrict__ k,
                                                const float* __restrict__ v,
                                                const float* __restrict__ Wq,
                                                const float* __restrict__ Wk,
                                                const float* __restrict__ Wv)
{
    const int bid = blockIdx.x;
    if (bid < 1024) {
        int warp = threadIdx.x >> 5;
        int lane = threadIdx.x & 31;
        int row  = bid * 8 + warp;
        const float2* qr = (const float2*)(q + (size_t)row * DIM);
        const float2* kr = (const float2*)(k + (size_t)row * DIM);
        const float2* vr = (const float2*)(v + (size_t)row * DIM);
        float sq = 0.f, sk = 0.f;
        #pragma unroll
        for (int it = 0; it < 8; it++) {
            int p = it * 32 + lane;
            size_t o = (size_t)row * 256 + p;
            u32 hi, lo;
            float2 x = qr[p]; sq += x.x + x.y;
            split_pair(x.x, x.y, hi, lo);
            ((u32*)g_Qrhi)[o] = hi; ((u32*)g_Qrlo)[o] = lo;
            x = kr[p]; sk += x.x + x.y;
            split_pair(x.x, x.y, hi, lo);
            ((u32*)g_Krhi)[o] = hi; ((u32*)g_Krlo)[o] = lo;
            x = vr[p];
            split_pair(x.x, x.y, hi, lo);
            ((u32*)g_Vrhi)[o] = hi; ((u32*)g_Vrlo)[o] = lo;
        }
        #pragma unroll
        for (int o = 16; o > 0; o >>= 1) {
            sq += __shfl_xor_sync(0xffffffffu, sq, o);
            sk += __shfl_xor_sync(0xffffffffu, sk, o);
        }
        if (lane == 0) {
            g_kbias[row] = (sk != 0.0f) ? 0.0f : NEG_INF_F * LOG2E;
            g_qmask[row] = (sq != 0.0f) ? 1.0f : 0.0f;
        }
    } else {
        int id  = bid - 1024;          // 0..1535
        int mat = id >> 9;             // 0..2
        int row = id & 511;
        int t   = threadIdx.x;
        const float* W = (mat == 0) ? Wq : (mat == 1) ? Wk : Wv;
        __nv_bfloat16* Whi = (mat == 0) ? g_Wqhi : (mat == 1) ? g_Wkhi : g_Wvhi;
        __nv_bfloat16* Wlo = (mat == 0) ? g_Wqlo : (mat == 1) ? g_Wklo : g_Wvlo;
        float2 x = ((const float2*)(W + (size_t)row * DIM))[t];
        u32 hi, lo;
        split_pair(x.x, x.y, hi, lo);
        ((u32*)Whi)[(size_t)row * 256 + t] = hi;
        ((u32*)Wlo)[(size_t)row * 256 + t] = lo;
    }
}

// ---------------------------------------------------------------------------
// Fused projection GEMM (z selects Q/K/V), pure bf16, cp.async 2-stage.
// CTA 128x128, 8 warps (4x2), warp tile 32x64, k-chunks of 32.
// Q output is pre-scaled by QSCALE = 0.125*log2e (feeds log2-domain softmax).
// ---------------------------------------------------------------------------
#define PA_RS 40
#define PW_RS 136
#define P_AH 0
#define P_AL (128*PA_RS*2)
#define P_WH (2*128*PA_RS*2)
#define P_WL (P_WH + 32*PW_RS*2)
#define P_STAGE (P_WL + 32*PW_RS*2)   // 37888
#define PROJ_SMEM (2*P_STAGE)         // 75776

__global__ void __launch_bounds__(256, 2) proj_mma(const float* __restrict__ bq,
                                                   const float* __restrict__ bk,
                                                   const float* __restrict__ bv)
{
    extern __shared__ char smc[];
    const u32 sb = smem_u32(smc);

    const int z = blockIdx.z;
    const __nv_bfloat16 *Ahi, *Alo, *Whi, *Wlo;
    __nv_bfloat16 *Chi, *Clo;
    const float* bias;
    float oscale;
    if (z == 0) { Ahi = g_Qrhi; Alo = g_Qrlo; Whi = g_Wqhi; Wlo = g_Wqlo;
                  Chi = g_Qhi;  Clo = g_Qlo;  bias = bq; oscale = QSCALE; }
    else if (z == 1) { Ahi = g_Krhi; Alo = g_Krlo; Whi = g_Wkhi; Wlo = g_Wklo;
                       Chi = g_Khi;  Clo = g_Klo;  bias = bk; oscale = 1.0f; }
    else { Ahi = g_Vrhi; Alo = g_Vrlo; Whi = g_Wvhi; Wlo = g_Wvlo;
           Chi = g_Vhi;  Clo = g_Vlo;  bias = bv; oscale = 1.0f; }

    const int tid  = threadIdx.x;
    const int warp = tid >> 5;
    const int lane = tid & 31;
    const int g    = lane >> 2;
    const int t4   = lane & 3;
    const int wr   = warp & 3;
    const int wc   = warp >> 2;
    const int bm   = blockIdx.y * 128;
    const int bn   = blockIdx.x * 128;

    const uint4* ah4 = (const uint4*)Ahi;
    const uint4* al4 = (const uint4*)Alo;
    const uint4* wh4 = (const uint4*)Whi;
    const uint4* wl4 = (const uint4*)Wlo;

    auto load_chunk = [&](int kc, int st) {
        int k0 = kc * 32;
        u32 base = sb + st * P_STAGE;
        #pragma unroll
        for (int it = 0; it < 2; it++) {
            int c = it * 256 + tid;
            {
                int r = c >> 2, gc = c & 3;
                size_t gi = ((size_t)(bm + r) * DIM + k0) / 8 + gc;
                u32 so = (u32)(r * PA_RS * 2 + gc * 16);
                cp16(base + P_AH + so, ah4 + gi);
                cp16(base + P_AL + so, al4 + gi);
            }
            {
                int r = c >> 4, gc = c & 15;
                size_t gi = ((size_t)(k0 + r) * DIM + bn) / 8 + gc;
                u32 so = (u32)(r * PW_RS * 2 + gc * 16);
                cp16(base + P_WH + so, wh4 + gi);
                cp16(base + P_WL + so, wl4 + gi);
            }
        }
    };

    const u32 aoff = (u32)(((wr * 32 + (lane & 15)) * PA_RS + ((lane >> 4) << 3)) * 2);
    const u32 woff = (u32)(((((lane & 7) + (lane & 8)) * PW_RS) +
                            wc * 64 + (((lane >> 4) << 3))) * 2);

    float acc[2][8][4];
    #pragma unroll
    for (int mt = 0; mt < 2; mt++)
        #pragma unroll
        for (int nt = 0; nt < 8; nt++)
            #pragma unroll
            for (int c = 0; c < 4; c++) acc[mt][nt][c] = 0.f;

    load_chunk(0, 0);
    CP_COMMIT();

    for (int kc = 0; kc < DIM / 32; kc++) {
        const int st = kc & 1;
        if (kc + 1 < DIM / 32) {
            load_chunk(kc + 1, st ^ 1);
            CP_COMMIT();
            CP_WAIT1();
        } else {
            CP_WAIT0();
        }
        __syncthreads();

        const u32 pb = sb + st * P_STAGE;
        #pragma unroll
        for (int kk = 0; kk < 2; kk++) {
            u32 ah[2][4], al[2][4];
            #pragma unroll
            for (int mt = 0; mt < 2; mt++) {
                u32 ao = aoff + (u32)((mt * 16 * PA_RS + kk * 16) * 2);
                ldm4(pb + P_AH + ao, ah[mt][0], ah[mt][1], ah[mt][2], ah[mt][3]);
                ldm4(pb + P_AL + ao, al[mt][0], al[mt][1], al[mt][2], al[mt][3]);
            }
            #pragma unroll
            for (int nt2 = 0; nt2 < 4; nt2++) {
                u32 wh[4], wl[4];
                u32 wo = woff + (u32)((kk * 16 * PW_RS + nt2 * 16) * 2);
                ldm4t(pb + P_WH + wo, wh[0], wh[1], wh[2], wh[3]);
                ldm4t(pb + P_WL + wo, wl[0], wl[1], wl[2], wl[3]);
                #pragma unroll
                for (int mt = 0; mt < 2; mt++) {
                    mma16816(acc[mt][2*nt2],   ah[mt][0], ah[mt][1], ah[mt][2], ah[mt][3], wh[0], wh[1]);
                    mma16816(acc[mt][2*nt2],   ah[mt][0], ah[mt][1], ah[mt][2], ah[mt][3], wl[0], wl[1]);
                    mma16816(acc[mt][2*nt2],   al[mt][0], al[mt][1], al[mt][2], al[mt][3], wh[0], wh[1]);
                    mma16816(acc[mt][2*nt2+1], ah[mt][0], ah[mt][1], ah[mt][2], ah[mt][3], wh[2], wh[3]);
                    mma16816(acc[mt][2*nt2+1], ah[mt][0], ah[mt][1], ah[mt][2], ah[mt][3], wl[2], wl[3]);
                    mma16816(acc[mt][2*nt2+1], al[mt][0], al[mt][1], al[mt][2], al[mt][3], wh[2], wh[3]);
                }
            }
        }
        __syncthreads();
    }

    // ---- epilogue: bias + relu (+Q scale), split to bf16 hi/lo ----
    #pragma unroll
    for (int mt = 0; mt < 2; mt++) {
        int r0 = bm + wr * 32 + mt * 16 + g;
        int r1 = r0 + 8;
        #pragma unroll
        for (int nt = 0; nt < 8; nt++) {
            int col = bn + wc * 64 + nt * 8 + 2 * t4;
            float b0 = bias[col], b1 = bias[col + 1];
            float v0 = fmaxf(acc[mt][nt][0] + b0, 0.f) * oscale;
            float v1 = fmaxf(acc[mt][nt][1] + b1, 0.f) * oscale;
            float v2 = fmaxf(acc[mt][nt][2] + b0, 0.f) * oscale;
            float v3 = fmaxf(acc[mt][nt][3] + b1, 0.f) * oscale;
            u32 hi, lo;
            split_pair(v0, v1, hi, lo);
            *(u32*)&Chi[(size_t)r0 * DIM + col] = hi;
            *(u32*)&Clo[(size_t)r0 * DIM + col] = lo;
            split_pair(v2, v3, hi, lo);
            *(u32*)&Chi[(size_t)r1 * DIM + col] = hi;
            *(u32*)&Clo[(size_t)r1 * DIM + col] = lo;
        }
    }
}

// ---------------------------------------------------------------------------
// mma.sync flash attention, log2-domain softmax, cp.async 2-stage K/V.
// CTA: 256 thr (8 warps), 128 q-rows x one hb; key tiles of 64.
// ---------------------------------------------------------------------------
#define RS    72
#define KVB   (64*RS*2)
#define KV_STAGE (4*KVB)
#define SMB_QHI 0
#define SMB_QLO (128*RS*2)
#define SMB_KV  (2*128*RS*2)
#define ATT_SMEM (SMB_KV + 2*KV_STAGE)  // 110592

__global__ void __launch_bounds__(256, 2) attn_kernel(float* __restrict__ Og)
{
    extern __shared__ char smc[];
    const u32 sb = smem_u32(smc);

    const int tid  = threadIdx.x;
    const int warp = tid >> 5;
    const int lane = tid & 31;
    const int g    = lane >> 2;
    const int t4   = lane & 3;
    const int hb   = blockIdx.y;
    const int head = hb >> 2;
    const int b    = hb & 3;
    const int qt0  = blockIdx.x * 128;

    // ---- Q tile (plain stores; covered by first __syncthreads) ----
    {
        const uint4* qh4 = (const uint4*)g_Qhi;
        const uint4* ql4 = (const uint4*)g_Qlo;
        #pragma unroll
        for (int it = 0; it < 4; it++) {
            int c = it * 256 + tid;
            int q = c >> 3, dc = c & 7;
            size_t gi = ((size_t)(b * SEQ + qt0 + q) * DIM + head * DHEAD) / 8 + dc;
            *(uint4*)(smc + SMB_QHI + q * (RS*2) + dc * 16) = qh4[gi];
            *(uint4*)(smc + SMB_QLO + q * (RS*2) + dc * 16) = ql4[gi];
        }
    }

    const uint4* kh4 = (const uint4*)g_Khi;
    const uint4* kl4 = (const uint4*)g_Klo;
    const uint4* vh4 = (const uint4*)g_Vhi;
    const uint4* vl4 = (const uint4*)g_Vlo;

    auto load_tile = [&](int kt, int st) {
        int k0 = kt * 64;
        u32 base = sb + SMB_KV + st * KV_STAGE;
        #pragma unroll
        for (int it = 0; it < 2; it++) {
            int c = it * 256 + tid;
            int r = c >> 3, dc = c & 7;
            size_t gi = ((size_t)(b * SEQ + k0 + r) * DIM + head * DHEAD) / 8 + dc;
            u32 so = (u32)(r * (RS*2) + dc * 16);
            cp16(base + 0*KVB + so, kh4 + gi);
            cp16(base + 1*KVB + so, kl4 + gi);
            cp16(base + 2*KVB + so, vh4 + gi);
            cp16(base + 3*KVB + so, vl4 + gi);
        }
    };

    const u32 aoff = (u32)((warp * 16 + (lane & 15)) * (RS*2) + ((lane >> 4) << 3) * 2);
    const u32 boff = (u32)((((lane & 7) + ((lane >> 4) << 3)) * (RS*2)) + ((((lane >> 3) & 1) << 3) * 2));
    const u32 voff = (u32)((((lane & 7) + (lane & 8)) * (RS*2)) + (((lane >> 4) << 3) * 2));

    float m0 = NEG_INF_F, m1 = NEG_INF_F, l0 = 0.f, l1 = 0.f;
    float oacc[8][4];
    #pragma unroll
    for (int j = 0; j < 8; j++)
        #pragma unroll
        for (int c = 0; c < 4; c++) oacc[j][c] = 0.f;

    load_tile(0, 0);
    CP_COMMIT();

    for (int kt = 0; kt < SEQ / 64; kt++) {
        const int st = kt & 1;
        const int k0 = kt * 64;

        // additive key-mask bias (0 in practice; exact no-op when mask=1)
        float km[8][2];
        #pragma unroll
        for (int j = 0; j < 8; j++) {
            km[j][0] = g_kbias[b * SEQ + k0 + 8*j + 2*t4];
            km[j][1] = g_kbias[b * SEQ + k0 + 8*j + 2*t4 + 1];
        }

        if (kt + 1 < SEQ / 64) {
            load_tile(kt + 1, st ^ 1);
            CP_COMMIT();
            CP_WAIT1();
        } else {
            CP_WAIT0();
        }
        __syncthreads();

        const u32 kb = sb + SMB_KV + st * KV_STAGE;

        // ---- GEMM1: S(log2 domain) = Qs K^T (hi*hi + hi*lo + lo*hi) ----
        float sacc[8][4];
        #pragma unroll
        for (int j = 0; j < 8; j++)
            #pragma unroll
            for (int c = 0; c < 4; c++) sacc[j][c] = 0.f;

        #pragma unroll
        for (int kk = 0; kk < 4; kk++) {
            u32 qh[4], ql[4];
            ldm4(sb + SMB_QHI + aoff + kk * 32, qh[0], qh[1], qh[2], qh[3]);
            ldm4(sb + SMB_QLO + aoff + kk * 32, ql[0], ql[1], ql[2], ql[3]);
            #pragma unroll
            for (int nt2 = 0; nt2 < 4; nt2++) {
                u32 kh[4], kl[4];
                u32 ko = boff + nt2 * 16 * (RS*2) + kk * 32;
                ldm4(kb + 0*KVB + ko, kh[0], kh[1], kh[2], kh[3]);
                ldm4(kb + 1*KVB + ko, kl[0], kl[1], kl[2], kl[3]);
                mma16816(sacc[2*nt2],   qh[0], qh[1], qh[2], qh[3], kh[0], kh[1]);
                mma16816(sacc[2*nt2],   qh[0], qh[1], qh[2], qh[3], kl[0], kl[1]);
                mma16816(sacc[2*nt2],   ql[0], ql[1], ql[2], ql[3], kh[0], kh[1]);
                mma16816(sacc[2*nt2+1], qh[0], qh[1], qh[2], qh[3], kh[2], kh[3]);
                mma16816(sacc[2*nt2+1], qh[0], qh[1], qh[2], qh[3], kl[2], kl[3]);
                mma16816(sacc[2*nt2+1], ql[0], ql[1], ql[2], ql[3], kh[2], kh[3]);
            }
        }

        // ---- additive mask bias ----
        #pragma unroll
        for (int j = 0; j < 8; j++) {
            sacc[j][0] += km[j][0];
            sacc[j][1] += km[j][1];
            sacc[j][2] += km[j][0];
            sacc[j][3] += km[j][1];
        }

        // ---- online softmax in log2 domain (rows g and g+8) ----
        float mx0 = NEG_INF_F, mx1 = NEG_INF_F;
        #pragma unroll
        for (int j = 0; j < 8; j++) {
            mx0 = fmaxf(mx0, fmaxf(sacc[j][0], sacc[j][1]));
            mx1 = fmaxf(mx1, fmaxf(sacc[j][2], sacc[j][3]));
        }
        mx0 = fmaxf(mx0, __shfl_xor_sync(0xffffffffu, mx0, 1));
        mx0 = fmaxf(mx0, __shfl_xor_sync(0xffffffffu, mx0, 2));
        mx1 = fmaxf(mx1, __shfl_xor_sync(0xffffffffu, mx1, 1));
        mx1 = fmaxf(mx1, __shfl_xor_sync(0xffffffffu, mx1, 2));

        float mn0 = fmaxf(m0, mx0), mn1 = fmaxf(m1, mx1);
        float a0 = ex2(m0 - mn0), a1 = ex2(m1 - mn1);
        m0 = mn0; m1 = mn1;

        float s0 = 0.f, s1 = 0.f;
        #pragma unroll
        for (int j = 0; j < 8; j++) {
            float p0 = ex2(sacc[j][0] - mn0);
            float p1 = ex2(sacc[j][1] - mn0);
            float p2 = ex2(sacc[j][2] - mn1);
            float p3 = ex2(sacc[j][3] - mn1);
            sacc[j][0] = p0; sacc[j][1] = p1; sacc[j][2] = p2; sacc[j][3] = p3;
            s0 += p0 + p1; s1 += p2 + p3;
        }
        s0 += __shfl_xor_sync(0xffffffffu, s0, 1);
        s0 += __shfl_xor_sync(0xffffffffu, s0, 2);
        s1 += __shfl_xor_sync(0xffffffffu, s1, 1);
        s1 += __shfl_xor_sync(0xffffffffu, s1, 2);
        l0 = l0 * a0 + s0;
        l1 = l1 * a1 + s1;

        #pragma unroll
        for (int j = 0; j < 8; j++) {
            oacc[j][0] *= a0; oacc[j][1] *= a0;
            oacc[j][2] *= a1; oacc[j][3] *= a1;
        }

        // ---- GEMM2: O += P V (hi*hi + hi*lo + lo*hi) ----
        #pragma unroll
        for (int kk = 0; kk < 4; kk++) {
            u32 ph[4], pl[4];
            #pragma unroll
            for (int h = 0; h < 2; h++) {
                int j = 2 * kk + h;
                float p0 = sacc[j][0], p1 = sacc[j][1], p2 = sacc[j][2], p3 = sacc[j][3];
                u32 h01 = pack_pair(p0, p1);
                u32 h23 = pack_pair(p2, p3);
                __nv_bfloat162 b01 = *(__nv_bfloat162*)&h01;
                __nv_bfloat162 b23 = *(__nv_bfloat162*)&h23;
                ph[2*h + 0] = h01;
                ph[2*h + 1] = h23;
                pl[2*h + 0] = pack_pair(p0 - __bfloat162float(b01.x),
                                        p1 - __bfloat162float(b01.y));
                pl[2*h + 1] = pack_pair(p2 - __bfloat162float(b23.x),
                                        p3 - __bfloat162float(b23.y));
            }
            u32 A0 = ph[0], A1 = ph[1], A2 = ph[2], A3 = ph[3];
            u32 L0 = pl[0], L1 = pl[1], L2 = pl[2], L3 = pl[3];

            #pragma unroll
            for (int dt2 = 0; dt2 < 4; dt2++) {
                u32 vh[4], vl[4];
                u32 vo = voff + kk * 16 * (RS*2) + dt2 * 32;
                ldm4t(kb + 2*KVB + vo, vh[0], vh[1], vh[2], vh[3]);
                ldm4t(kb + 3*KVB + vo, vl[0], vl[1], vl[2], vl[3]);
                mma16816(oacc[2*dt2],   A0, A1, A2, A3, vh[0], vh[1]);
                mma16816(oacc[2*dt2],   A0, A1, A2, A3, vl[0], vl[1]);
                mma16816(oacc[2*dt2],   L0, L1, L2, L3, vh[0], vh[1]);
                mma16816(oacc[2*dt2+1], A0, A1, A2, A3, vh[2], vh[3]);
                mma16816(oacc[2*dt2+1], A0, A1, A2, A3, vl[2], vl[3]);
                mma16816(oacc[2*dt2+1], L0, L1, L2, L3, vh[2], vh[3]);
            }
        }
        __syncthreads();
    }

    // ---- epilogue: normalize, query mask, write ----
    {
        int q0 = qt0 + warp * 16 + g;
        int q1 = q0 + 8;
        float inv0 = g_qmask[b * SEQ + q0] / l0;
        float inv1 = g_qmask[b * SEQ + q1] / l1;
        size_t base0 = (size_t)(b * SEQ + q0) * DIM + head * DHEAD;
        size_t base1 = (size_t)(b * SEQ + q1) * DIM + head * DHEAD;
        #pragma unroll
        for (int j = 0; j < 8; j++) {
            int d = 8 * j + 2 * t4;
            *(float2*)&Og[base0 + d] = make_float2(oacc[j][0] * inv0, oacc[j][1] * inv0);
            *(float2*)&Og[base1 + d] = make_float2(oacc[j][2] * inv1, oacc[j][3] * inv1);
        }
    }
}

// ---------------------------------------------------------------------------
// Residual + LayerNorm (ddof=1, eps added to std). Block per row, 128 threads.
// ---------------------------------------------------------------------------
__device__ __forceinline__ float block_sum_128(float v, float* red)
{
    #pragma unroll
    for (int o = 16; o > 0; o >>= 1) v += __shfl_xor_sync(0xffffffffu, v, o);
    int lane = threadIdx.x & 31, w = threadIdx.x >> 5;
    if (lane == 0) red[w] = v;
    __syncthreads();
    float t = red[0] + red[1] + red[2] + red[3];
    __syncthreads();
    return t;
}

__global__ void __launch_bounds__(128) ln_kernel(const float* __restrict__ queries,
                                                 const float* __restrict__ gamma,
                                                 const float* __restrict__ beta,
                                                 float* __restrict__ out)
{
    __shared__ float red[4];
    const int row = blockIdx.x;
    const int tid = threadIdx.x;
    const size_t rb = (size_t)row * DIM;

    float x[4];
    #pragma unroll
    for (int u = 0; u < 4; u++) {
        int c = tid + u * 128;
        x[u] = g_O[rb + c] + queries[rb + c];
    }
    float s = x[0] + x[1] + x[2] + x[3];
    float total = block_sum_128(s, red);
    float mean = total * (1.0f / DIM);

    float ss = 0.f;
    #pragma unroll
    for (int u = 0; u < 4; u++) { float d = x[u] - mean; ss += d * d; }
    float sstot = block_sum_128(ss, red);
    float var = sstot * (1.0f / (DIM - 1));
    float rden = 1.0f / (sqrtf(var) + LN_EPS);

    #pragma unroll
    for (int u = 0; u < 4; u++) {
        int c = tid + u * 128;
        out[rb + c] = gamma[c] * (x[u] - mean) * rden + beta[c];
    }
}

// ---------------------------------------------------------------------------
extern "C" void kernel_launch(void* const* d_in, const int* in_sizes, int n_in,
                              void* d_out, int out_size)
{
    const float* queries = (const float*)d_in[0];
    const float* keys    = (const float*)d_in[1];
    const float* values  = (const float*)d_in[2];
    const float* Wq      = (const float*)d_in[3];
    const float* bq      = (const float*)d_in[4];
    const float* Wk      = (const float*)d_in[5];
    const float* bk      = (const float*)d_in[6];
    const float* Wv      = (const float*)d_in[7];
    const float* bv      = (const float*)d_in[8];
    const float* gamma   = (const float*)d_in[9];
    const float* beta    = (const float*)d_in[10];
    float* out = (float*)d_out;

    float* pO;
    cudaGetSymbolAddress((void**)&pO, g_O);

    cudaFuncSetAttribute(attn_kernel, cudaFuncAttributeMaxDynamicSharedMemorySize, ATT_SMEM);
    cudaFuncSetAttribute(proj_mma, cudaFuncAttributeMaxDynamicSharedMemorySize, PROJ_SMEM);

    // 1. masks + input splits + weight splits (one fused launch)
    prep_all<<<2560, 256>>>(queries, keys, values, Wq, Wk, Wv);

    // 2. all three projections in one launch (z = Q/K/V)
    proj_mma<<<dim3(DIM / 128, MROWS / 128, 3), 256, PROJ_SMEM>>>(bq, bk, bv);

    // 3. mma.sync flash attention (log2-domain softmax)
    attn_kernel<<<dim3(SEQ / 128, HB), 256, ATT_SMEM>>>(pO);

    // 4. residual + layernorm
    ln_kernel<<<MROWS, 128>>>(queries, gamma, beta, out);
}

// round 14
// speedup vs baseline: 7.2176x; 1.2156x over previous
#include <cuda_runtime.h>
#include <cuda_bf16.h>
#include <math.h>

#define BATCH 4
#define SEQ   2048
#define DIM   512
#define NHEAD 8
#define DHEAD 64
#define MROWS (BATCH*SEQ)      // 8192
#define HB    (NHEAD*BATCH)    // 32

#define NEG_INF_F (-4294967295.0f)   // -(2^32 - 1)
#define LOG2E     1.4426950408889634f
#define QSCALE    (0.125f * LOG2E)   // folded into Q projection epilogue
#define LN_EPS 1e-8f

typedef unsigned int u32;

// ---------------------------------------------------------------------------
// Scratch (no allocation allowed in kernel_launch)
// ---------------------------------------------------------------------------
static __device__ __nv_bfloat16 g_Qhi[MROWS*DIM];
static __device__ __nv_bfloat16 g_Qlo[MROWS*DIM];
static __device__ __nv_bfloat16 g_Khi[MROWS*DIM];
static __device__ __nv_bfloat16 g_Klo[MROWS*DIM];
static __device__ __nv_bfloat16 g_Vhi[MROWS*DIM];
static __device__ __nv_bfloat16 g_Vlo[MROWS*DIM];
static __device__ __nv_bfloat16 g_Qrhi[MROWS*DIM];
static __device__ __nv_bfloat16 g_Qrlo[MROWS*DIM];
static __device__ __nv_bfloat16 g_Krhi[MROWS*DIM];
static __device__ __nv_bfloat16 g_Krlo[MROWS*DIM];
static __device__ __nv_bfloat16 g_Vrhi[MROWS*DIM];
static __device__ __nv_bfloat16 g_Vrlo[MROWS*DIM];
static __device__ __nv_bfloat16 g_Wqhi[DIM*DIM];
static __device__ __nv_bfloat16 g_Wqlo[DIM*DIM];
static __device__ __nv_bfloat16 g_Wkhi[DIM*DIM];
static __device__ __nv_bfloat16 g_Wklo[DIM*DIM];
static __device__ __nv_bfloat16 g_Wvhi[DIM*DIM];
static __device__ __nv_bfloat16 g_Wvlo[DIM*DIM];

static __device__ float g_O[MROWS*DIM];
static __device__ float g_kbias[MROWS];   // 0 or NEG_INF*log2e (additive, log2 domain)
static __device__ float g_qmask[MROWS];

// ---------------------------------------------------------------------------
// helpers
// ---------------------------------------------------------------------------
__device__ __forceinline__ u32 smem_u32(const void* p) {
    u32 a;
    asm("{ .reg .u64 t; cvta.to.shared.u64 t, %1; cvt.u32.u64 %0, t; }" : "=r"(a) : "l"(p));
    return a;
}
__device__ __forceinline__ void ldm4(u32 addr, u32& r0, u32& r1, u32& r2, u32& r3) {
    asm volatile("ldmatrix.sync.aligned.m8n8.x4.shared.b16 {%0,%1,%2,%3}, [%4];"
                 : "=r"(r0), "=r"(r1), "=r"(r2), "=r"(r3) : "r"(addr));
}
__device__ __forceinline__ void ldm4t(u32 addr, u32& r0, u32& r1, u32& r2, u32& r3) {
    asm volatile("ldmatrix.sync.aligned.m8n8.x4.trans.shared.b16 {%0,%1,%2,%3}, [%4];"
                 : "=r"(r0), "=r"(r1), "=r"(r2), "=r"(r3) : "r"(addr));
}
__device__ __forceinline__ void mma16816(float d[4], u32 a0, u32 a1, u32 a2, u32 a3,
                                         u32 b0, u32 b1) {
    asm volatile("mma.sync.aligned.m16n8k16.row.col.f32.bf16.bf16.f32 "
                 "{%0,%1,%2,%3}, {%4,%5,%6,%7}, {%8,%9}, {%0,%1,%2,%3};"
                 : "+f"(d[0]), "+f"(d[1]), "+f"(d[2]), "+f"(d[3])
                 : "r"(a0), "r"(a1), "r"(a2), "r"(a3), "r"(b0), "r"(b1));
}
__device__ __forceinline__ u32 pack_pair(float lo, float hi) {
    __nv_bfloat162 t = __halves2bfloat162(__float2bfloat16(lo), __float2bfloat16(hi));
    return *(u32*)&t;
}
__device__ __forceinline__ void split_pair(float v0, float v1, u32& hi, u32& lo) {
    __nv_bfloat16 h0 = __float2bfloat16(v0);
    __nv_bfloat16 h1 = __float2bfloat16(v1);
    __nv_bfloat162 hh = __halves2bfloat162(h0, h1);
    __nv_bfloat162 ll = __halves2bfloat162(__float2bfloat16(v0 - __bfloat162float(h0)),
                                           __float2bfloat16(v1 - __bfloat162float(h1)));
    hi = *(u32*)&hh;
    lo = *(u32*)&ll;
}
__device__ __forceinline__ void cp16(u32 dst, const void* src) {
    asm volatile("cp.async.cg.shared.global [%0], [%1], 16;" :: "r"(dst), "l"(src));
}
#define CP_COMMIT() asm volatile("cp.async.commit_group;" ::: "memory")
#define CP_WAIT1()  asm volatile("cp.async.wait_group 1;" ::: "memory")
#define CP_WAIT0()  asm volatile("cp.async.wait_group 0;" ::: "memory")
__device__ __forceinline__ float ex2(float x) {
    float r;
    asm("ex2.approx.f32 %0, %1;" : "=f"(r) : "f"(x));
    return r;
}

// ---------------------------------------------------------------------------
// prep_all: blocks [0,1024): masks/kbias + input splits (warp per row)
//           blocks [1024,2560): weight splits (block per row, 3 matrices)
// ---------------------------------------------------------------------------
__global__ void __launch_bounds__(256) prep_all(const float* __restrict__ q,
                                                const float* __restrict__ k,
                                                const float* __restrict__ v,
                                                const float* __restrict__ Wq,
                                                const float* __restrict__ Wk,
                                                const float* __restrict__ Wv)
{
    const int bid = blockIdx.x;
    if (bid < 1024) {
        int warp = threadIdx.x >> 5;
        int lane = threadIdx.x & 31;
        int row  = bid * 8 + warp;
        const float2* qr = (const float2*)(q + (size_t)row * DIM);
        const float2* kr = (const float2*)(k + (size_t)row * DIM);
        const float2* vr = (const float2*)(v + (size_t)row * DIM);
        float sq = 0.f, sk = 0.f;
        #pragma unroll
        for (int it = 0; it < 8; it++) {
            int p = it * 32 + lane;
            size_t o = (size_t)row * 256 + p;
            u32 hi, lo;
            float2 x = qr[p]; sq += x.x + x.y;
            split_pair(x.x, x.y, hi, lo);
            ((u32*)g_Qrhi)[o] = hi; ((u32*)g_Qrlo)[o] = lo;
            x = kr[p]; sk += x.x + x.y;
            split_pair(x.x, x.y, hi, lo);
            ((u32*)g_Krhi)[o] = hi; ((u32*)g_Krlo)[o] = lo;
            x = vr[p];
            split_pair(x.x, x.y, hi, lo);
            ((u32*)g_Vrhi)[o] = hi; ((u32*)g_Vrlo)[o] = lo;
        }
        #pragma unroll
        for (int o = 16; o > 0; o >>= 1) {
            sq += __shfl_xor_sync(0xffffffffu, sq, o);
            sk += __shfl_xor_sync(0xffffffffu, sk, o);
        }
        if (lane == 0) {
            g_kbias[row] = (sk != 0.0f) ? 0.0f : NEG_INF_F * LOG2E;
            g_qmask[row] = (sq != 0.0f) ? 1.0f : 0.0f;
        }
    } else {
        int id  = bid - 1024;          // 0..1535
        int mat = id >> 9;             // 0..2
        int row = id & 511;
        int t   = threadIdx.x;
        const float* W = (mat == 0) ? Wq : (mat == 1) ? Wk : Wv;
        __nv_bfloat16* Whi = (mat == 0) ? g_Wqhi : (mat == 1) ? g_Wkhi : g_Wvhi;
        __nv_bfloat16* Wlo = (mat == 0) ? g_Wqlo : (mat == 1) ? g_Wklo : g_Wvlo;
        float2 x = ((const float2*)(W + (size_t)row * DIM))[t];
        u32 hi, lo;
        split_pair(x.x, x.y, hi, lo);
        ((u32*)Whi)[(size_t)row * 256 + t] = hi;
        ((u32*)Wlo)[(size_t)row * 256 + t] = lo;
    }
}

// ---------------------------------------------------------------------------
// Fused projection GEMM (z selects Q/K/V), pure bf16, cp.async 2-stage.
// CTA 128x128, 8 warps (4x2), warp tile 32x64, k-chunks of 32.
// Q output is pre-scaled by QSCALE = 0.125*log2e (feeds log2-domain softmax).
// ---------------------------------------------------------------------------
#define PA_RS 40
#define PW_RS 136
#define P_AH 0
#define P_AL (128*PA_RS*2)
#define P_WH (2*128*PA_RS*2)
#define P_WL (P_WH + 32*PW_RS*2)
#define P_STAGE (P_WL + 32*PW_RS*2)   // 37888
#define PROJ_SMEM (2*P_STAGE)         // 75776

__global__ void __launch_bounds__(256, 2) proj_mma(const float* __restrict__ bq,
                                                   const float* __restrict__ bk,
                                                   const float* __restrict__ bv)
{
    extern __shared__ char smc[];
    const u32 sb = smem_u32(smc);

    const int z = blockIdx.z;
    const __nv_bfloat16 *Ahi, *Alo, *Whi, *Wlo;
    __nv_bfloat16 *Chi, *Clo;
    const float* bias;
    float oscale;
    if (z == 0) { Ahi = g_Qrhi; Alo = g_Qrlo; Whi = g_Wqhi; Wlo = g_Wqlo;
                  Chi = g_Qhi;  Clo = g_Qlo;  bias = bq; oscale = QSCALE; }
    else if (z == 1) { Ahi = g_Krhi; Alo = g_Krlo; Whi = g_Wkhi; Wlo = g_Wklo;
                       Chi = g_Khi;  Clo = g_Klo;  bias = bk; oscale = 1.0f; }
    else { Ahi = g_Vrhi; Alo = g_Vrlo; Whi = g_Wvhi; Wlo = g_Wvlo;
           Chi = g_Vhi;  Clo = g_Vlo;  bias = bv; oscale = 1.0f; }

    const int tid  = threadIdx.x;
    const int warp = tid >> 5;
    const int lane = tid & 31;
    const int g    = lane >> 2;
    const int t4   = lane & 3;
    const int wr   = warp & 3;
    const int wc   = warp >> 2;
    const int bm   = blockIdx.y * 128;
    const int bn   = blockIdx.x * 128;

    const uint4* ah4 = (const uint4*)Ahi;
    const uint4* al4 = (const uint4*)Alo;
    const uint4* wh4 = (const uint4*)Whi;
    const uint4* wl4 = (const uint4*)Wlo;

    auto load_chunk = [&](int kc, int st) {
        int k0 = kc * 32;
        u32 base = sb + st * P_STAGE;
        #pragma unroll
        for (int it = 0; it < 2; it++) {
            int c = it * 256 + tid;
            {
                int r = c >> 2, gc = c & 3;
                size_t gi = ((size_t)(bm + r) * DIM + k0) / 8 + gc;
                u32 so = (u32)(r * PA_RS * 2 + gc * 16);
                cp16(base + P_AH + so, ah4 + gi);
                cp16(base + P_AL + so, al4 + gi);
            }
            {
                int r = c >> 4, gc = c & 15;
                size_t gi = ((size_t)(k0 + r) * DIM + bn) / 8 + gc;
                u32 so = (u32)(r * PW_RS * 2 + gc * 16);
                cp16(base + P_WH + so, wh4 + gi);
                cp16(base + P_WL + so, wl4 + gi);
            }
        }
    };

    const u32 aoff = (u32)(((wr * 32 + (lane & 15)) * PA_RS + ((lane >> 4) << 3)) * 2);
    const u32 woff = (u32)(((((lane & 7) + (lane & 8)) * PW_RS) +
                            wc * 64 + (((lane >> 4) << 3))) * 2);

    float acc[2][8][4];
    #pragma unroll
    for (int mt = 0; mt < 2; mt++)
        #pragma unroll
        for (int nt = 0; nt < 8; nt++)
            #pragma unroll
            for (int c = 0; c < 4; c++) acc[mt][nt][c] = 0.f;

    load_chunk(0, 0);
    CP_COMMIT();

    for (int kc = 0; kc < DIM / 32; kc++) {
        const int st = kc & 1;
        if (kc + 1 < DIM / 32) {
            load_chunk(kc + 1, st ^ 1);
            CP_COMMIT();
            CP_WAIT1();
        } else {
            CP_WAIT0();
        }
        __syncthreads();

        const u32 pb = sb + st * P_STAGE;
        #pragma unroll
        for (int kk = 0; kk < 2; kk++) {
            u32 ah[2][4], al[2][4];
            #pragma unroll
            for (int mt = 0; mt < 2; mt++) {
                u32 ao = aoff + (u32)((mt * 16 * PA_RS + kk * 16) * 2);
                ldm4(pb + P_AH + ao, ah[mt][0], ah[mt][1], ah[mt][2], ah[mt][3]);
                ldm4(pb + P_AL + ao, al[mt][0], al[mt][1], al[mt][2], al[mt][3]);
            }
            #pragma unroll
            for (int nt2 = 0; nt2 < 4; nt2++) {
                u32 wh[4], wl[4];
                u32 wo = woff + (u32)((kk * 16 * PW_RS + nt2 * 16) * 2);
                ldm4t(pb + P_WH + wo, wh[0], wh[1], wh[2], wh[3]);
                ldm4t(pb + P_WL + wo, wl[0], wl[1], wl[2], wl[3]);
                #pragma unroll
                for (int mt = 0; mt < 2; mt++) {
                    mma16816(acc[mt][2*nt2],   ah[mt][0], ah[mt][1], ah[mt][2], ah[mt][3], wh[0], wh[1]);
                    mma16816(acc[mt][2*nt2],   ah[mt][0], ah[mt][1], ah[mt][2], ah[mt][3], wl[0], wl[1]);
                    mma16816(acc[mt][2*nt2],   al[mt][0], al[mt][1], al[mt][2], al[mt][3], wh[0], wh[1]);
                    mma16816(acc[mt][2*nt2+1], ah[mt][0], ah[mt][1], ah[mt][2], ah[mt][3], wh[2], wh[3]);
                    mma16816(acc[mt][2*nt2+1], ah[mt][0], ah[mt][1], ah[mt][2], ah[mt][3], wl[2], wl[3]);
                    mma16816(acc[mt][2*nt2+1], al[mt][0], al[mt][1], al[mt][2], al[mt][3], wh[2], wh[3]);
                }
            }
        }
        __syncthreads();
    }

    // ---- epilogue: bias + relu (+Q scale), split to bf16 hi/lo ----
    #pragma unroll
    for (int mt = 0; mt < 2; mt++) {
        int r0 = bm + wr * 32 + mt * 16 + g;
        int r1 = r0 + 8;
        #pragma unroll
        for (int nt = 0; nt < 8; nt++) {
            int col = bn + wc * 64 + nt * 8 + 2 * t4;
            float b0 = bias[col], b1 = bias[col + 1];
            float v0 = fmaxf(acc[mt][nt][0] + b0, 0.f) * oscale;
            float v1 = fmaxf(acc[mt][nt][1] + b1, 0.f) * oscale;
            float v2 = fmaxf(acc[mt][nt][2] + b0, 0.f) * oscale;
            float v3 = fmaxf(acc[mt][nt][3] + b1, 0.f) * oscale;
            u32 hi, lo;
            split_pair(v0, v1, hi, lo);
            *(u32*)&Chi[(size_t)r0 * DIM + col] = hi;
            *(u32*)&Clo[(size_t)r0 * DIM + col] = lo;
            split_pair(v2, v3, hi, lo);
            *(u32*)&Chi[(size_t)r1 * DIM + col] = hi;
            *(u32*)&Clo[(size_t)r1 * DIM + col] = lo;
        }
    }
}

// ---------------------------------------------------------------------------
// mma.sync flash attention, log2-domain softmax, cp.async 2-stage K/V.
// 2-product split: S = Qhi*(Khi+Klo), O = Phi*(Vhi+Vlo).
// CTA: 256 thr (8 warps), 128 q-rows x one hb; key tiles of 64.
// ---------------------------------------------------------------------------
#define RS    72
#define KVB   (64*RS*2)
#define KV_STAGE (4*KVB)
#define SMB_QHI 0
#define SMB_KV  (128*RS*2)              // 18432 (Q hi only now)
#define ATT_SMEM (SMB_KV + 2*KV_STAGE)  // 92160

__global__ void __launch_bounds__(256, 2) attn_kernel(float* __restrict__ Og)
{
    extern __shared__ char smc[];
    const u32 sb = smem_u32(smc);

    const int tid  = threadIdx.x;
    const int warp = tid >> 5;
    const int lane = tid & 31;
    const int g    = lane >> 2;
    const int t4   = lane & 3;
    const int hb   = blockIdx.y;
    const int head = hb >> 2;
    const int b    = hb & 3;
    const int qt0  = blockIdx.x * 128;

    // ---- Q tile (hi only; plain stores, covered by first __syncthreads) ----
    {
        const uint4* qh4 = (const uint4*)g_Qhi;
        #pragma unroll
        for (int it = 0; it < 4; it++) {
            int c = it * 256 + tid;
            int q = c >> 3, dc = c & 7;
            size_t gi = ((size_t)(b * SEQ + qt0 + q) * DIM + head * DHEAD) / 8 + dc;
            *(uint4*)(smc + SMB_QHI + q * (RS*2) + dc * 16) = qh4[gi];
        }
    }

    const uint4* kh4 = (const uint4*)g_Khi;
    const uint4* kl4 = (const uint4*)g_Klo;
    const uint4* vh4 = (const uint4*)g_Vhi;
    const uint4* vl4 = (const uint4*)g_Vlo;

    auto load_tile = [&](int kt, int st) {
        int k0 = kt * 64;
        u32 base = sb + SMB_KV + st * KV_STAGE;
        #pragma unroll
        for (int it = 0; it < 2; it++) {
            int c = it * 256 + tid;
            int r = c >> 3, dc = c & 7;
            size_t gi = ((size_t)(b * SEQ + k0 + r) * DIM + head * DHEAD) / 8 + dc;
            u32 so = (u32)(r * (RS*2) + dc * 16);
            cp16(base + 0*KVB + so, kh4 + gi);
            cp16(base + 1*KVB + so, kl4 + gi);
            cp16(base + 2*KVB + so, vh4 + gi);
            cp16(base + 3*KVB + so, vl4 + gi);
        }
    };

    const u32 aoff = (u32)((warp * 16 + (lane & 15)) * (RS*2) + ((lane >> 4) << 3) * 2);
    const u32 boff = (u32)((((lane & 7) + ((lane >> 4) << 3)) * (RS*2)) + ((((lane >> 3) & 1) << 3) * 2));
    const u32 voff = (u32)((((lane & 7) + (lane & 8)) * (RS*2)) + (((lane >> 4) << 3) * 2));

    float m0 = NEG_INF_F, m1 = NEG_INF_F, l0 = 0.f, l1 = 0.f;
    float oacc[8][4];
    #pragma unroll
    for (int j = 0; j < 8; j++)
        #pragma unroll
        for (int c = 0; c < 4; c++) oacc[j][c] = 0.f;

    load_tile(0, 0);
    CP_COMMIT();

    for (int kt = 0; kt < SEQ / 64; kt++) {
        const int st = kt & 1;
        const int k0 = kt * 64;

        // additive key-mask bias (0 in practice; exact no-op when mask=1)
        float km[8][2];
        #pragma unroll
        for (int j = 0; j < 8; j++) {
            km[j][0] = g_kbias[b * SEQ + k0 + 8*j + 2*t4];
            km[j][1] = g_kbias[b * SEQ + k0 + 8*j + 2*t4 + 1];
        }

        if (kt + 1 < SEQ / 64) {
            load_tile(kt + 1, st ^ 1);
            CP_COMMIT();
            CP_WAIT1();
        } else {
            CP_WAIT0();
        }
        __syncthreads();

        const u32 kb = sb + SMB_KV + st * KV_STAGE;

        // ---- GEMM1: S(log2 domain) = Qhi (Khi + Klo)^T  (2 products) ----
        float sacc[8][4];
        #pragma unroll
        for (int j = 0; j < 8; j++)
            #pragma unroll
            for (int c = 0; c < 4; c++) sacc[j][c] = 0.f;

        #pragma unroll
        for (int kk = 0; kk < 4; kk++) {
            u32 qh[4];
            ldm4(sb + SMB_QHI + aoff + kk * 32, qh[0], qh[1], qh[2], qh[3]);
            #pragma unroll
            for (int nt2 = 0; nt2 < 4; nt2++) {
                u32 kh[4], kl[4];
                u32 ko = boff + nt2 * 16 * (RS*2) + kk * 32;
                ldm4(kb + 0*KVB + ko, kh[0], kh[1], kh[2], kh[3]);
                ldm4(kb + 1*KVB + ko, kl[0], kl[1], kl[2], kl[3]);
                mma16816(sacc[2*nt2],   qh[0], qh[1], qh[2], qh[3], kh[0], kh[1]);
                mma16816(sacc[2*nt2],   qh[0], qh[1], qh[2], qh[3], kl[0], kl[1]);
                mma16816(sacc[2*nt2+1], qh[0], qh[1], qh[2], qh[3], kh[2], kh[3]);
                mma16816(sacc[2*nt2+1], qh[0], qh[1], qh[2], qh[3], kl[2], kl[3]);
            }
        }

        // ---- additive mask bias ----
        #pragma unroll
        for (int j = 0; j < 8; j++) {
            sacc[j][0] += km[j][0];
            sacc[j][1] += km[j][1];
            sacc[j][2] += km[j][0];
            sacc[j][3] += km[j][1];
        }

        // ---- online softmax in log2 domain (rows g and g+8) ----
        float mx0 = NEG_INF_F, mx1 = NEG_INF_F;
        #pragma unroll
        for (int j = 0; j < 8; j++) {
            mx0 = fmaxf(mx0, fmaxf(sacc[j][0], sacc[j][1]));
            mx1 = fmaxf(mx1, fmaxf(sacc[j][2], sacc[j][3]));
        }
        mx0 = fmaxf(mx0, __shfl_xor_sync(0xffffffffu, mx0, 1));
        mx0 = fmaxf(mx0, __shfl_xor_sync(0xffffffffu, mx0, 2));
        mx1 = fmaxf(mx1, __shfl_xor_sync(0xffffffffu, mx1, 1));
        mx1 = fmaxf(mx1, __shfl_xor_sync(0xffffffffu, mx1, 2));

        float mn0 = fmaxf(m0, mx0), mn1 = fmaxf(m1, mx1);
        float a0 = ex2(m0 - mn0), a1 = ex2(m1 - mn1);
        m0 = mn0; m1 = mn1;

        float s0 = 0.f, s1 = 0.f;
        #pragma unroll
        for (int j = 0; j < 8; j++) {
            float p0 = ex2(sacc[j][0] - mn0);
            float p1 = ex2(sacc[j][1] - mn0);
            float p2 = ex2(sacc[j][2] - mn1);
            float p3 = ex2(sacc[j][3] - mn1);
            sacc[j][0] = p0; sacc[j][1] = p1; sacc[j][2] = p2; sacc[j][3] = p3;
            s0 += p0 + p1; s1 += p2 + p3;
        }
        s0 += __shfl_xor_sync(0xffffffffu, s0, 1);
        s0 += __shfl_xor_sync(0xffffffffu, s0, 2);
        s1 += __shfl_xor_sync(0xffffffffu, s1, 1);
        s1 += __shfl_xor_sync(0xffffffffu, s1, 2);
        l0 = l0 * a0 + s0;
        l1 = l1 * a1 + s1;

        #pragma unroll
        for (int j = 0; j < 8; j++) {
            oacc[j][0] *= a0; oacc[j][1] *= a0;
            oacc[j][2] *= a1; oacc[j][3] *= a1;
        }

        // ---- GEMM2: O += Phi (Vhi + Vlo)  (2 products, single-bf16 P) ----
        #pragma unroll
        for (int kk = 0; kk < 4; kk++) {
            u32 ph[4];
            #pragma unroll
            for (int h = 0; h < 2; h++) {
                int j = 2 * kk + h;
                ph[2*h + 0] = pack_pair(sacc[j][0], sacc[j][1]);
                ph[2*h + 1] = pack_pair(sacc[j][2], sacc[j][3]);
            }
            u32 A0 = ph[0], A1 = ph[1], A2 = ph[2], A3 = ph[3];

            #pragma unroll
            for (int dt2 = 0; dt2 < 4; dt2++) {
                u32 vh[4], vl[4];
                u32 vo = voff + kk * 16 * (RS*2) + dt2 * 32;
                ldm4t(kb + 2*KVB + vo, vh[0], vh[1], vh[2], vh[3]);
                ldm4t(kb + 3*KVB + vo, vl[0], vl[1], vl[2], vl[3]);
                mma16816(oacc[2*dt2],   A0, A1, A2, A3, vh[0], vh[1]);
                mma16816(oacc[2*dt2],   A0, A1, A2, A3, vl[0], vl[1]);
                mma16816(oacc[2*dt2+1], A0, A1, A2, A3, vh[2], vh[3]);
                mma16816(oacc[2*dt2+1], A0, A1, A2, A3, vl[2], vl[3]);
            }
        }
        __syncthreads();
    }

    // ---- epilogue: normalize, query mask, write ----
    {
        int q0 = qt0 + warp * 16 + g;
        int q1 = q0 + 8;
        float inv0 = g_qmask[b * SEQ + q0] / l0;
        float inv1 = g_qmask[b * SEQ + q1] / l1;
        size_t base0 = (size_t)(b * SEQ + q0) * DIM + head * DHEAD;
        size_t base1 = (size_t)(b * SEQ + q1) * DIM + head * DHEAD;
        #pragma unroll
        for (int j = 0; j < 8; j++) {
            int d = 8 * j + 2 * t4;
            *(float2*)&Og[base0 + d] = make_float2(oacc[j][0] * inv0, oacc[j][1] * inv0);
            *(float2*)&Og[base1 + d] = make_float2(oacc[j][2] * inv1, oacc[j][3] * inv1);
        }
    }
}

// ---------------------------------------------------------------------------
// Residual + LayerNorm (ddof=1, eps added to std). Block per row, 128 threads.
// ---------------------------------------------------------------------------
__device__ __forceinline__ float block_sum_128(float v, float* red)
{
    #pragma unroll
    for (int o = 16; o > 0; o >>= 1) v += __shfl_xor_sync(0xffffffffu, v, o);
    int lane = threadIdx.x & 31, w = threadIdx.x >> 5;
    if (lane == 0) red[w] = v;
    __syncthreads();
    float t = red[0] + red[1] + red[2] + red[3];
    __syncthreads();
    return t;
}

__global__ void __launch_bounds__(128) ln_kernel(const float* __restrict__ queries,
                                                 const float* __restrict__ gamma,
                                                 const float* __restrict__ beta,
                                                 float* __restrict__ out)
{
    __shared__ float red[4];
    const int row = blockIdx.x;
    const int tid = threadIdx.x;
    const size_t rb = (size_t)row * DIM;

    float x[4];
    #pragma unroll
    for (int u = 0; u < 4; u++) {
        int c = tid + u * 128;
        x[u] = g_O[rb + c] + queries[rb + c];
    }
    float s = x[0] + x[1] + x[2] + x[3];
    float total = block_sum_128(s, red);
    float mean = total * (1.0f / DIM);

    float ss = 0.f;
    #pragma unroll
    for (int u = 0; u < 4; u++) { float d = x[u] - mean; ss += d * d; }
    float sstot = block_sum_128(ss, red);
    float var = sstot * (1.0f / (DIM - 1));
    float rden = 1.0f / (sqrtf(var) + LN_EPS);

    #pragma unroll
    for (int u = 0; u < 4; u++) {
        int c = tid + u * 128;
        out[rb + c] = gamma[c] * (x[u] - mean) * rden + beta[c];
    }
}

// ---------------------------------------------------------------------------
extern "C" void kernel_launch(void* const* d_in, const int* in_sizes, int n_in,
                              void* d_out, int out_size)
{
    const float* queries = (const float*)d_in[0];
    const float* keys    = (const float*)d_in[1];
    const float* values  = (const float*)d_in[2];
    const float* Wq      = (const float*)d_in[3];
    const float* bq      = (const float*)d_in[4];
    const float* Wk      = (const float*)d_in[5];
    const float* bk      = (const float*)d_in[6];
    const float* Wv      = (const float*)d_in[7];
    const float* bv      = (const float*)d_in[8];
    const float* gamma   = (const float*)d_in[9];
    const float* beta    = (const float*)d_in[10];
    float* out = (float*)d_out;

    float* pO;
    cudaGetSymbolAddress((void**)&pO, g_O);

    cudaFuncSetAttribute(attn_kernel, cudaFuncAttributeMaxDynamicSharedMemorySize, ATT_SMEM);
    cudaFuncSetAttribute(proj_mma, cudaFuncAttributeMaxDynamicSharedMemorySize, PROJ_SMEM);

    // 1. masks + input splits + weight splits (one fused launch)
    prep_all<<<2560, 256>>>(queries, keys, values, Wq, Wk, Wv);

    // 2. all three projections in one launch (z = Q/K/V)
    proj_mma<<<dim3(DIM / 128, MROWS / 128, 3), 256, PROJ_SMEM>>>(bq, bk, bv);

    // 3. mma.sync flash attention (log2-domain softmax, 2-product split)
    attn_kernel<<<dim3(SEQ / 128, HB), 256, ATT_SMEM>>>(pO);

    // 4. residual + layernorm
    ln_kernel<<<MROWS, 128>>>(queries, gamma, beta, out);
}

// round 15
// speedup vs baseline: 8.0233x; 1.1116x over previous
#include <cuda_runtime.h>
#include <cuda_bf16.h>
#include <math.h>

#define BATCH 4
#define SEQ   2048
#define DIM   512
#define NHEAD 8
#define DHEAD 64
#define MROWS (BATCH*SEQ)      // 8192
#define HB    (NHEAD*BATCH)    // 32

#define NEG_INF_F (-4294967295.0f)   // -(2^32 - 1)
#define LOG2E     1.4426950408889634f
#define QSCALE    (0.125f * LOG2E)   // folded into Q projection epilogue
#define LN_EPS 1e-8f

typedef unsigned int u32;

// ---------------------------------------------------------------------------
// Scratch (no allocation allowed in kernel_launch)
// ---------------------------------------------------------------------------
static __device__ __nv_bfloat16 g_Qhi[MROWS*DIM];
static __device__ __nv_bfloat16 g_Khi[MROWS*DIM];
static __device__ __nv_bfloat16 g_Klo[MROWS*DIM];
static __device__ __nv_bfloat16 g_Vhi[MROWS*DIM];
static __device__ __nv_bfloat16 g_Vlo[MROWS*DIM];
// raw input hi (projection GEMM A operand, single bf16)
static __device__ __nv_bfloat16 g_Qrhi[MROWS*DIM];
static __device__ __nv_bfloat16 g_Krhi[MROWS*DIM];
static __device__ __nv_bfloat16 g_Vrhi[MROWS*DIM];
// weight splits (kept hi/lo)
static __device__ __nv_bfloat16 g_Wqhi[DIM*DIM];
static __device__ __nv_bfloat16 g_Wqlo[DIM*DIM];
static __device__ __nv_bfloat16 g_Wkhi[DIM*DIM];
static __device__ __nv_bfloat16 g_Wklo[DIM*DIM];
static __device__ __nv_bfloat16 g_Wvhi[DIM*DIM];
static __device__ __nv_bfloat16 g_Wvlo[DIM*DIM];

static __device__ float g_O[MROWS*DIM];
static __device__ float g_kbias[MROWS];   // 0 or NEG_INF*log2e (additive, log2 domain)
static __device__ float g_qmask[MROWS];

// ---------------------------------------------------------------------------
// helpers
// ---------------------------------------------------------------------------
__device__ __forceinline__ u32 smem_u32(const void* p) {
    u32 a;
    asm("{ .reg .u64 t; cvta.to.shared.u64 t, %1; cvt.u32.u64 %0, t; }" : "=r"(a) : "l"(p));
    return a;
}
__device__ __forceinline__ void ldm4(u32 addr, u32& r0, u32& r1, u32& r2, u32& r3) {
    asm volatile("ldmatrix.sync.aligned.m8n8.x4.shared.b16 {%0,%1,%2,%3}, [%4];"
                 : "=r"(r0), "=r"(r1), "=r"(r2), "=r"(r3) : "r"(addr));
}
__device__ __forceinline__ void ldm4t(u32 addr, u32& r0, u32& r1, u32& r2, u32& r3) {
    asm volatile("ldmatrix.sync.aligned.m8n8.x4.trans.shared.b16 {%0,%1,%2,%3}, [%4];"
                 : "=r"(r0), "=r"(r1), "=r"(r2), "=r"(r3) : "r"(addr));
}
__device__ __forceinline__ void mma16816(float d[4], u32 a0, u32 a1, u32 a2, u32 a3,
                                         u32 b0, u32 b1) {
    asm volatile("mma.sync.aligned.m16n8k16.row.col.f32.bf16.bf16.f32 "
                 "{%0,%1,%2,%3}, {%4,%5,%6,%7}, {%8,%9}, {%0,%1,%2,%3};"
                 : "+f"(d[0]), "+f"(d[1]), "+f"(d[2]), "+f"(d[3])
                 : "r"(a0), "r"(a1), "r"(a2), "r"(a3), "r"(b0), "r"(b1));
}
__device__ __forceinline__ u32 pack_pair(float lo, float hi) {
    __nv_bfloat162 t = __halves2bfloat162(__float2bfloat16(lo), __float2bfloat16(hi));
    return *(u32*)&t;
}
__device__ __forceinline__ void split_pair(float v0, float v1, u32& hi, u32& lo) {
    __nv_bfloat16 h0 = __float2bfloat16(v0);
    __nv_bfloat16 h1 = __float2bfloat16(v1);
    __nv_bfloat162 hh = __halves2bfloat162(h0, h1);
    __nv_bfloat162 ll = __halves2bfloat162(__float2bfloat16(v0 - __bfloat162float(h0)),
                                           __float2bfloat16(v1 - __bfloat162float(h1)));
    hi = *(u32*)&hh;
    lo = *(u32*)&ll;
}
__device__ __forceinline__ void cp16(u32 dst, const void* src) {
    asm volatile("cp.async.cg.shared.global [%0], [%1], 16;" :: "r"(dst), "l"(src));
}
#define CP_COMMIT() asm volatile("cp.async.commit_group;" ::: "memory")
#define CP_WAIT1()  asm volatile("cp.async.wait_group 1;" ::: "memory")
#define CP_WAIT0()  asm volatile("cp.async.wait_group 0;" ::: "memory")
__device__ __forceinline__ float ex2(float x) {
    float r;
    asm("ex2.approx.f32 %0, %1;" : "=f"(r) : "f"(x));
    return r;
}

// ---------------------------------------------------------------------------
// prep_all: blocks [0,1024): masks/kbias + input bf16 (hi only; warp per row)
//           blocks [1024,2560): weight hi/lo splits (block per row, 3 matrices)
// ---------------------------------------------------------------------------
__global__ void __launch_bounds__(256) prep_all(const float* __restrict__ q,
                                                const float* __restrict__ k,
                                                const float* __restrict__ v,
                                                const float* __restrict__ Wq,
                                                const float* __restrict__ Wk,
                                                const float* __restrict__ Wv)
{
    const int bid = blockIdx.x;
    if (bid < 1024) {
        int warp = threadIdx.x >> 5;
        int lane = threadIdx.x & 31;
        int row  = bid * 8 + warp;
        const float2* qr = (const float2*)(q + (size_t)row * DIM);
        const float2* kr = (const float2*)(k + (size_t)row * DIM);
        const float2* vr = (const float2*)(v + (size_t)row * DIM);
        float sq = 0.f, sk = 0.f;
        #pragma unroll
        for (int it = 0; it < 8; it++) {
            int p = it * 32 + lane;
            size_t o = (size_t)row * 256 + p;
            float2 x = qr[p]; sq += x.x + x.y;
            ((u32*)g_Qrhi)[o] = pack_pair(x.x, x.y);
            x = kr[p]; sk += x.x + x.y;
            ((u32*)g_Krhi)[o] = pack_pair(x.x, x.y);
            x = vr[p];
            ((u32*)g_Vrhi)[o] = pack_pair(x.x, x.y);
        }
        #pragma unroll
        for (int o = 16; o > 0; o >>= 1) {
            sq += __shfl_xor_sync(0xffffffffu, sq, o);
            sk += __shfl_xor_sync(0xffffffffu, sk, o);
        }
        if (lane == 0) {
            g_kbias[row] = (sk != 0.0f) ? 0.0f : NEG_INF_F * LOG2E;
            g_qmask[row] = (sq != 0.0f) ? 1.0f : 0.0f;
        }
    } else {
        int id  = bid - 1024;          // 0..1535
        int mat = id >> 9;             // 0..2
        int row = id & 511;
        int t   = threadIdx.x;
        const float* W = (mat == 0) ? Wq : (mat == 1) ? Wk : Wv;
        __nv_bfloat16* Whi = (mat == 0) ? g_Wqhi : (mat == 1) ? g_Wkhi : g_Wvhi;
        __nv_bfloat16* Wlo = (mat == 0) ? g_Wqlo : (mat == 1) ? g_Wklo : g_Wvlo;
        float2 x = ((const float2*)(W + (size_t)row * DIM))[t];
        u32 hi, lo;
        split_pair(x.x, x.y, hi, lo);
        ((u32*)Whi)[(size_t)row * 256 + t] = hi;
        ((u32*)Wlo)[(size_t)row * 256 + t] = lo;
    }
}

// ---------------------------------------------------------------------------
// Fused projection GEMM (z selects Q/K/V): C = relu(Ahi (Whi+Wlo) + b).
// 2-product: single-bf16 A, split W. cp.async 2-stage pipeline.
// CTA 128x128, 8 warps (4x2), warp tile 32x64, k-chunks of 32.
// Q output is pre-scaled by QSCALE and stores hi only (attn uses Qhi only).
// ---------------------------------------------------------------------------
#define PA_RS 40
#define PW_RS 136
#define P_AH 0
#define P_WH (128*PA_RS*2)            // 10240
#define P_WL (P_WH + 32*PW_RS*2)      // 18944
#define P_STAGE (P_WL + 32*PW_RS*2)   // 27648
#define PROJ_SMEM (2*P_STAGE)         // 55296

__global__ void __launch_bounds__(256, 2) proj_mma(const float* __restrict__ bq,
                                                   const float* __restrict__ bk,
                                                   const float* __restrict__ bv)
{
    extern __shared__ char smc[];
    const u32 sb = smem_u32(smc);

    const int z = blockIdx.z;
    const __nv_bfloat16 *Ahi, *Whi, *Wlo;
    __nv_bfloat16 *Chi, *Clo;
    const float* bias;
    float oscale;
    if (z == 0) { Ahi = g_Qrhi; Whi = g_Wqhi; Wlo = g_Wqlo;
                  Chi = g_Qhi;  Clo = 0;      bias = bq; oscale = QSCALE; }
    else if (z == 1) { Ahi = g_Krhi; Whi = g_Wkhi; Wlo = g_Wklo;
                       Chi = g_Khi;  Clo = g_Klo;  bias = bk; oscale = 1.0f; }
    else { Ahi = g_Vrhi; Whi = g_Wvhi; Wlo = g_Wvlo;
           Chi = g_Vhi;  Clo = g_Vlo;  bias = bv; oscale = 1.0f; }

    const int tid  = threadIdx.x;
    const int warp = tid >> 5;
    const int lane = tid & 31;
    const int g    = lane >> 2;
    const int t4   = lane & 3;
    const int wr   = warp & 3;
    const int wc   = warp >> 2;
    const int bm   = blockIdx.y * 128;
    const int bn   = blockIdx.x * 128;

    const uint4* ah4 = (const uint4*)Ahi;
    const uint4* wh4 = (const uint4*)Whi;
    const uint4* wl4 = (const uint4*)Wlo;

    auto load_chunk = [&](int kc, int st) {
        int k0 = kc * 32;
        u32 base = sb + st * P_STAGE;
        #pragma unroll
        for (int it = 0; it < 2; it++) {
            int c = it * 256 + tid;
            {
                int r = c >> 2, gc = c & 3;
                size_t gi = ((size_t)(bm + r) * DIM + k0) / 8 + gc;
                u32 so = (u32)(r * PA_RS * 2 + gc * 16);
                cp16(base + P_AH + so, ah4 + gi);
            }
            {
                int r = c >> 4, gc = c & 15;
                size_t gi = ((size_t)(k0 + r) * DIM + bn) / 8 + gc;
                u32 so = (u32)(r * PW_RS * 2 + gc * 16);
                cp16(base + P_WH + so, wh4 + gi);
                cp16(base + P_WL + so, wl4 + gi);
            }
        }
    };

    const u32 aoff = (u32)(((wr * 32 + (lane & 15)) * PA_RS + ((lane >> 4) << 3)) * 2);
    const u32 woff = (u32)(((((lane & 7) + (lane & 8)) * PW_RS) +
                            wc * 64 + (((lane >> 4) << 3))) * 2);

    float acc[2][8][4];
    #pragma unroll
    for (int mt = 0; mt < 2; mt++)
        #pragma unroll
        for (int nt = 0; nt < 8; nt++)
            #pragma unroll
            for (int c = 0; c < 4; c++) acc[mt][nt][c] = 0.f;

    load_chunk(0, 0);
    CP_COMMIT();

    for (int kc = 0; kc < DIM / 32; kc++) {
        const int st = kc & 1;
        if (kc + 1 < DIM / 32) {
            load_chunk(kc + 1, st ^ 1);
            CP_COMMIT();
            CP_WAIT1();
        } else {
            CP_WAIT0();
        }
        __syncthreads();

        const u32 pb = sb + st * P_STAGE;
        #pragma unroll
        for (int kk = 0; kk < 2; kk++) {
            u32 ah[2][4];
            #pragma unroll
            for (int mt = 0; mt < 2; mt++) {
                u32 ao = aoff + (u32)((mt * 16 * PA_RS + kk * 16) * 2);
                ldm4(pb + P_AH + ao, ah[mt][0], ah[mt][1], ah[mt][2], ah[mt][3]);
            }
            #pragma unroll
            for (int nt2 = 0; nt2 < 4; nt2++) {
                u32 wh[4], wl[4];
                u32 wo = woff + (u32)((kk * 16 * PW_RS + nt2 * 16) * 2);
                ldm4t(pb + P_WH + wo, wh[0], wh[1], wh[2], wh[3]);
                ldm4t(pb + P_WL + wo, wl[0], wl[1], wl[2], wl[3]);
                #pragma unroll
                for (int mt = 0; mt < 2; mt++) {
                    mma16816(acc[mt][2*nt2],   ah[mt][0], ah[mt][1], ah[mt][2], ah[mt][3], wh[0], wh[1]);
                    mma16816(acc[mt][2*nt2],   ah[mt][0], ah[mt][1], ah[mt][2], ah[mt][3], wl[0], wl[1]);
                    mma16816(acc[mt][2*nt2+1], ah[mt][0], ah[mt][1], ah[mt][2], ah[mt][3], wh[2], wh[3]);
                    mma16816(acc[mt][2*nt2+1], ah[mt][0], ah[mt][1], ah[mt][2], ah[mt][3], wl[2], wl[3]);
                }
            }
        }
        __syncthreads();
    }

    // ---- epilogue: bias + relu (+Q scale), split to bf16 hi/lo ----
    #pragma unroll
    for (int mt = 0; mt < 2; mt++) {
        int r0 = bm + wr * 32 + mt * 16 + g;
        int r1 = r0 + 8;
        #pragma unroll
        for (int nt = 0; nt < 8; nt++) {
            int col = bn + wc * 64 + nt * 8 + 2 * t4;
            float b0 = bias[col], b1 = bias[col + 1];
            float v0 = fmaxf(acc[mt][nt][0] + b0, 0.f) * oscale;
            float v1 = fmaxf(acc[mt][nt][1] + b1, 0.f) * oscale;
            float v2 = fmaxf(acc[mt][nt][2] + b0, 0.f) * oscale;
            float v3 = fmaxf(acc[mt][nt][3] + b1, 0.f) * oscale;
            if (z == 0) {
                *(u32*)&Chi[(size_t)r0 * DIM + col] = pack_pair(v0, v1);
                *(u32*)&Chi[(size_t)r1 * DIM + col] = pack_pair(v2, v3);
            } else {
                u32 hi, lo;
                split_pair(v0, v1, hi, lo);
                *(u32*)&Chi[(size_t)r0 * DIM + col] = hi;
                *(u32*)&Clo[(size_t)r0 * DIM + col] = lo;
                split_pair(v2, v3, hi, lo);
                *(u32*)&Chi[(size_t)r1 * DIM + col] = hi;
                *(u32*)&Clo[(size_t)r1 * DIM + col] = lo;
            }
        }
    }
}

// ---------------------------------------------------------------------------
// mma.sync flash attention, log2-domain softmax, cp.async 2-stage K/V.
// 2-product split: S = Qhi*(Khi+Klo), O = Phi*(Vhi+Vlo).
// CTA: 256 thr (8 warps), 128 q-rows x one hb; key tiles of 64.
// ---------------------------------------------------------------------------
#define RS    72
#define KVB   (64*RS*2)
#define KV_STAGE (4*KVB)
#define SMB_QHI 0
#define SMB_KV  (128*RS*2)              // 18432 (Q hi only)
#define ATT_SMEM (SMB_KV + 2*KV_STAGE)  // 92160

__global__ void __launch_bounds__(256, 2) attn_kernel(float* __restrict__ Og)
{
    extern __shared__ char smc[];
    const u32 sb = smem_u32(smc);

    const int tid  = threadIdx.x;
    const int warp = tid >> 5;
    const int lane = tid & 31;
    const int g    = lane >> 2;
    const int t4   = lane & 3;
    const int hb   = blockIdx.y;
    const int head = hb >> 2;
    const int b    = hb & 3;
    const int qt0  = blockIdx.x * 128;

    // ---- Q tile (hi only; plain stores, covered by first __syncthreads) ----
    {
        const uint4* qh4 = (const uint4*)g_Qhi;
        #pragma unroll
        for (int it = 0; it < 4; it++) {
            int c = it * 256 + tid;
            int q = c >> 3, dc = c & 7;
            size_t gi = ((size_t)(b * SEQ + qt0 + q) * DIM + head * DHEAD) / 8 + dc;
            *(uint4*)(smc + SMB_QHI + q * (RS*2) + dc * 16) = qh4[gi];
        }
    }

    const uint4* kh4 = (const uint4*)g_Khi;
    const uint4* kl4 = (const uint4*)g_Klo;
    const uint4* vh4 = (const uint4*)g_Vhi;
    const uint4* vl4 = (const uint4*)g_Vlo;

    auto load_tile = [&](int kt, int st) {
        int k0 = kt * 64;
        u32 base = sb + SMB_KV + st * KV_STAGE;
        #pragma unroll
        for (int it = 0; it < 2; it++) {
            int c = it * 256 + tid;
            int r = c >> 3, dc = c & 7;
            size_t gi = ((size_t)(b * SEQ + k0 + r) * DIM + head * DHEAD) / 8 + dc;
            u32 so = (u32)(r * (RS*2) + dc * 16);
            cp16(base + 0*KVB + so, kh4 + gi);
            cp16(base + 1*KVB + so, kl4 + gi);
            cp16(base + 2*KVB + so, vh4 + gi);
            cp16(base + 3*KVB + so, vl4 + gi);
        }
    };

    const u32 aoff = (u32)((warp * 16 + (lane & 15)) * (RS*2) + ((lane >> 4) << 3) * 2);
    const u32 boff = (u32)((((lane & 7) + ((lane >> 4) << 3)) * (RS*2)) + ((((lane >> 3) & 1) << 3) * 2));
    const u32 voff = (u32)((((lane & 7) + (lane & 8)) * (RS*2)) + (((lane >> 4) << 3) * 2));

    float m0 = NEG_INF_F, m1 = NEG_INF_F, l0 = 0.f, l1 = 0.f;
    float oacc[8][4];
    #pragma unroll
    for (int j = 0; j < 8; j++)
        #pragma unroll
        for (int c = 0; c < 4; c++) oacc[j][c] = 0.f;

    load_tile(0, 0);
    CP_COMMIT();

    for (int kt = 0; kt < SEQ / 64; kt++) {
        const int st = kt & 1;
        const int k0 = kt * 64;

        // additive key-mask bias (0 in practice; exact no-op when mask=1)
        float km[8][2];
        #pragma unroll
        for (int j = 0; j < 8; j++) {
            km[j][0] = g_kbias[b * SEQ + k0 + 8*j + 2*t4];
            km[j][1] = g_kbias[b * SEQ + k0 + 8*j + 2*t4 + 1];
        }

        if (kt + 1 < SEQ / 64) {
            load_tile(kt + 1, st ^ 1);
            CP_COMMIT();
            CP_WAIT1();
        } else {
            CP_WAIT0();
        }
        __syncthreads();

        const u32 kb = sb + SMB_KV + st * KV_STAGE;

        // ---- GEMM1: S(log2 domain) = Qhi (Khi + Klo)^T  (2 products) ----
        float sacc[8][4];
        #pragma unroll
        for (int j = 0; j < 8; j++)
            #pragma unroll
            for (int c = 0; c < 4; c++) sacc[j][c] = 0.f;

        #pragma unroll
        for (int kk = 0; kk < 4; kk++) {
            u32 qh[4];
            ldm4(sb + SMB_QHI + aoff + kk * 32, qh[0], qh[1], qh[2], qh[3]);
            #pragma unroll
            for (int nt2 = 0; nt2 < 4; nt2++) {
                u32 kh[4], kl[4];
                u32 ko = boff + nt2 * 16 * (RS*2) + kk * 32;
                ldm4(kb + 0*KVB + ko, kh[0], kh[1], kh[2], kh[3]);
                ldm4(kb + 1*KVB + ko, kl[0], kl[1], kl[2], kl[3]);
                mma16816(sacc[2*nt2],   qh[0], qh[1], qh[2], qh[3], kh[0], kh[1]);
                mma16816(sacc[2*nt2],   qh[0], qh[1], qh[2], qh[3], kl[0], kl[1]);
                mma16816(sacc[2*nt2+1], qh[0], qh[1], qh[2], qh[3], kh[2], kh[3]);
                mma16816(sacc[2*nt2+1], qh[0], qh[1], qh[2], qh[3], kl[2], kl[3]);
            }
        }

        // ---- additive mask bias ----
        #pragma unroll
        for (int j = 0; j < 8; j++) {
            sacc[j][0] += km[j][0];
            sacc[j][1] += km[j][1];
            sacc[j][2] += km[j][0];
            sacc[j][3] += km[j][1];
        }

        // ---- online softmax in log2 domain (rows g and g+8) ----
        float mx0 = NEG_INF_F, mx1 = NEG_INF_F;
        #pragma unroll
        for (int j = 0; j < 8; j++) {
            mx0 = fmaxf(mx0, fmaxf(sacc[j][0], sacc[j][1]));
            mx1 = fmaxf(mx1, fmaxf(sacc[j][2], sacc[j][3]));
        }
        mx0 = fmaxf(mx0, __shfl_xor_sync(0xffffffffu, mx0, 1));
        mx0 = fmaxf(mx0, __shfl_xor_sync(0xffffffffu, mx0, 2));
        mx1 = fmaxf(mx1, __shfl_xor_sync(0xffffffffu, mx1, 1));
        mx1 = fmaxf(mx1, __shfl_xor_sync(0xffffffffu, mx1, 2));

        float mn0 = fmaxf(m0, mx0), mn1 = fmaxf(m1, mx1);
        float a0 = ex2(m0 - mn0), a1 = ex2(m1 - mn1);
        m0 = mn0; m1 = mn1;

        float s0 = 0.f, s1 = 0.f;
        #pragma unroll
        for (int j = 0; j < 8; j++) {
            float p0 = ex2(sacc[j][0] - mn0);
            float p1 = ex2(sacc[j][1] - mn0);
            float p2 = ex2(sacc[j][2] - mn1);
            float p3 = ex2(sacc[j][3] - mn1);
            sacc[j][0] = p0; sacc[j][1] = p1; sacc[j][2] = p2; sacc[j][3] = p3;
            s0 += p0 + p1; s1 += p2 + p3;
        }
        s0 += __shfl_xor_sync(0xffffffffu, s0, 1);
        s0 += __shfl_xor_sync(0xffffffffu, s0, 2);
        s1 += __shfl_xor_sync(0xffffffffu, s1, 1);
        s1 += __shfl_xor_sync(0xffffffffu, s1, 2);
        l0 = l0 * a0 + s0;
        l1 = l1 * a1 + s1;

        #pragma unroll
        for (int j = 0; j < 8; j++) {
            oacc[j][0] *= a0; oacc[j][1] *= a0;
            oacc[j][2] *= a1; oacc[j][3] *= a1;
        }

        // ---- GEMM2: O += Phi (Vhi + Vlo)  (2 products, single-bf16 P) ----
        #pragma unroll
        for (int kk = 0; kk < 4; kk++) {
            u32 ph[4];
            #pragma unroll
            for (int h = 0; h < 2; h++) {
                int j = 2 * kk + h;
                ph[2*h + 0] = pack_pair(sacc[j][0], sacc[j][1]);
                ph[2*h + 1] = pack_pair(sacc[j][2], sacc[j][3]);
            }
            u32 A0 = ph[0], A1 = ph[1], A2 = ph[2], A3 = ph[3];

            #pragma unroll
            for (int dt2 = 0; dt2 < 4; dt2++) {
                u32 vh[4], vl[4];
                u32 vo = voff + kk * 16 * (RS*2) + dt2 * 32;
                ldm4t(kb + 2*KVB + vo, vh[0], vh[1], vh[2], vh[3]);
                ldm4t(kb + 3*KVB + vo, vl[0], vl[1], vl[2], vl[3]);
                mma16816(oacc[2*dt2],   A0, A1, A2, A3, vh[0], vh[1]);
                mma16816(oacc[2*dt2],   A0, A1, A2, A3, vl[0], vl[1]);
                mma16816(oacc[2*dt2+1], A0, A1, A2, A3, vh[2], vh[3]);
                mma16816(oacc[2*dt2+1], A0, A1, A2, A3, vl[2], vl[3]);
            }
        }
        __syncthreads();
    }

    // ---- epilogue: normalize, query mask, write ----
    {
        int q0 = qt0 + warp * 16 + g;
        int q1 = q0 + 8;
        float inv0 = g_qmask[b * SEQ + q0] / l0;
        float inv1 = g_qmask[b * SEQ + q1] / l1;
        size_t base0 = (size_t)(b * SEQ + q0) * DIM + head * DHEAD;
        size_t base1 = (size_t)(b * SEQ + q1) * DIM + head * DHEAD;
        #pragma unroll
        for (int j = 0; j < 8; j++) {
            int d = 8 * j + 2 * t4;
            *(float2*)&Og[base0 + d] = make_float2(oacc[j][0] * inv0, oacc[j][1] * inv0);
            *(float2*)&Og[base1 + d] = make_float2(oacc[j][2] * inv1, oacc[j][3] * inv1);
        }
    }
}

// ---------------------------------------------------------------------------
// Residual + LayerNorm (ddof=1, eps added to std). Block per row, 128 threads.
// ---------------------------------------------------------------------------
__device__ __forceinline__ float block_sum_128(float v, float* red)
{
    #pragma unroll
    for (int o = 16; o > 0; o >>= 1) v += __shfl_xor_sync(0xffffffffu, v, o);
    int lane = threadIdx.x & 31, w = threadIdx.x >> 5;
    if (lane == 0) red[w] = v;
    __syncthreads();
    float t = red[0] + red[1] + red[2] + red[3];
    __syncthreads();
    return t;
}

__global__ void __launch_bounds__(128) ln_kernel(const float* __restrict__ queries,
                                                 const float* __restrict__ gamma,
                                                 const float* __restrict__ beta,
                                                 float* __restrict__ out)
{
    __shared__ float red[4];
    const int row = blockIdx.x;
    const int tid = threadIdx.x;
    const size_t rb = (size_t)row * DIM;

    float x[4];
    #pragma unroll
    for (int u = 0; u < 4; u++) {
        int c = tid + u * 128;
        x[u] = g_O[rb + c] + queries[rb + c];
    }
    float s = x[0] + x[1] + x[2] + x[3];
    float total = block_sum_128(s, red);
    float mean = total * (1.0f / DIM);

    float ss = 0.f;
    #pragma unroll
    for (int u = 0; u < 4; u++) { float d = x[u] - mean; ss += d * d; }
    float sstot = block_sum_128(ss, red);
    float var = sstot * (1.0f / (DIM - 1));
    float rden = 1.0f / (sqrtf(var) + LN_EPS);

    #pragma unroll
    for (int u = 0; u < 4; u++) {
        int c = tid + u * 128;
        out[rb + c] = gamma[c] * (x[u] - mean) * rden + beta[c];
    }
}

// ---------------------------------------------------------------------------
extern "C" void kernel_launch(void* const* d_in, const int* in_sizes, int n_in,
                              void* d_out, int out_size)
{
    const float* queries = (const float*)d_in[0];
    const float* keys    = (const float*)d_in[1];
    const float* values  = (const float*)d_in[2];
    const float* Wq      = (const float*)d_in[3];
    const float* bq      = (const float*)d_in[4];
    const float* Wk      = (const float*)d_in[5];
    const float* bk      = (const float*)d_in[6];
    const float* Wv      = (const float*)d_in[7];
    const float* bv      = (const float*)d_in[8];
    const float* gamma   = (const float*)d_in[9];
    const float* beta    = (const float*)d_in[10];
    float* out = (float*)d_out;

    float* pO;
    cudaGetSymbolAddress((void**)&pO, g_O);

    cudaFuncSetAttribute(attn_kernel, cudaFuncAttributeMaxDynamicSharedMemorySize, ATT_SMEM);
    cudaFuncSetAttribute(proj_mma, cudaFuncAttributeMaxDynamicSharedMemorySize, PROJ_SMEM);

    // 1. masks + input bf16 + weight splits (one fused launch)
    prep_all<<<2560, 256>>>(queries, keys, values, Wq, Wk, Wv);

    // 2. all three projections in one launch (z = Q/K/V), 2-product
    proj_mma<<<dim3(DIM / 128, MROWS / 128, 3), 256, PROJ_SMEM>>>(bq, bk, bv);

    // 3. mma.sync flash attention (log2-domain softmax, 2-product split)
    attn_kernel<<<dim3(SEQ / 128, HB), 256, ATT_SMEM>>>(pO);

    // 4. residual + layernorm
    ln_kernel<<<MROWS, 128>>>(queries, gamma, beta, out);
}